// round 12
// baseline (speedup 1.0000x reference)
#include <cuda_runtime.h>
#include <cuda_fp16.h>
#include <math.h>
#include <stdint.h>

// ---------------------------------------------------------------------------
// StarTransformerLayer, GB300 (compute_103 -> mma.sync path).
// B=8, L=4096, H=256, NH=8, HD=32, 2 iterations.
// Sat GEMMs: fp16 in / fp32 accum; R12: QKV outputs stored fp16 (bandwidth),
// Wo output (LN residual input) stays fp32. Calibrated error ~6e-4 < 1e-3.
// Rel attention: GEMM-free, scores fused into ln_rows (R11).
// ---------------------------------------------------------------------------

namespace {
constexpr int Bn  = 8;
constexpr int Ln  = 4096;
constexpr int Hn  = 256;
constexpr int NHn = 8;
constexpr int HDn = 32;
constexpr int Mn  = Bn * Ln;          // 32768
constexpr int KA  = 256;              // fp16 A columns
constexpr int SCW = 4128;             // score row stride (4097 used)
constexpr int NSP = 32;               // wsum chunks (128 keys each)
constexpr float SCALE = 0.17677669529663688f;   // 1/sqrt(32)
constexpr float LNEPS = 1e-12f;
// GEMM tiling
constexpr int KC   = 32;
constexpr int NC   = KA / KC;         // 8 chunks
constexpr int LDA  = 40;              // 32 + 8 pad (halfs)
constexpr int LDB  = 264;             // 256 + 8 pad (halfs)
constexpr int ASZ  = 128 * LDA;       // 5120 halfs
constexpr int BSZ  = KC * LDB;        // 8448 halfs
constexpr int STG  = ASZ + BSZ;       // 13568 halfs
constexpr int GEMM_SMEM = STG * 2 * 4;   // 108544 bytes (4 stages)
}

// ---- scratch (device globals) ---------------------------------------------
__device__ float  g_cur [Mn * Hn];
__device__ __align__(16) __half g_curP[(size_t)Mn * KA];
__device__ __align__(16) __half g_ctxP[(size_t)Mn * KA];
__device__ __align__(16) __half g_BT  [4 * (size_t)Hn * Hn];
// fp16 attention operands (sat_attn consumers only)
__device__ __align__(16) __half g_Qh [(size_t)Mn * Hn];
__device__ __align__(16) __half g_Kch[(size_t)Mn * Hn];
__device__ __align__(16) __half g_Vch[(size_t)Mn * Hn];
__device__ __align__(16) __half g_Kxh[(size_t)Mn * Hn];
__device__ __align__(16) __half g_Vxh[(size_t)Mn * Hn];
__device__ float  g_tmp [Mn * Hn];

__device__ float g_center[Bn * Hn];
// center projections, 8 k-partials: [ks][sel][b*Hn+n]; sel 0=Kcen 1=Vcen 2=Qrel
__device__ float g_cproj[8][3][Bn * Hn];
__device__ float g_cpart[Bn * 16 * Hn];

// rel attention scratch
__device__ float g_wtil[64 * Hn];            // per (b,h): w~ (includes SCALE)
__device__ float g_sc  [64 * SCW];           // scores, jidx 0..4096
__device__ float g_pm  [64];                 // per-bh max
__device__ float g_ps  [64];                 // per-bh sum-exp
__device__ float g_upart[(size_t)Bn * NSP * NHn * Hn];   // partial wsums

// ---------------------------------------------------------------------------
// helpers
// ---------------------------------------------------------------------------
__device__ __forceinline__ uint32_t smem_u32(const void* p) {
    uint32_t a;
    asm("{ .reg .u64 t; cvta.to.shared.u64 t, %1; cvt.u32.u64 %0, t; }"
        : "=r"(a) : "l"(p));
    return a;
}
__device__ __forceinline__ void cp16(uint32_t s, const void* g) {
    asm volatile("cp.async.cg.shared.global [%0], [%1], 16;" :: "r"(s), "l"(g));
}
__device__ __forceinline__ void cp_commit() {
    asm volatile("cp.async.commit_group;" ::: "memory");
}
__device__ __forceinline__ void ldm_x4(uint32_t* r, uint32_t a) {
    asm volatile("ldmatrix.sync.aligned.m8n8.x4.shared.b16 {%0,%1,%2,%3}, [%4];"
                 : "=r"(r[0]), "=r"(r[1]), "=r"(r[2]), "=r"(r[3]) : "r"(a));
}
__device__ __forceinline__ void ldm_x4t(uint32_t* r, uint32_t a) {
    asm volatile("ldmatrix.sync.aligned.m8n8.x4.trans.shared.b16 {%0,%1,%2,%3}, [%4];"
                 : "=r"(r[0]), "=r"(r[1]), "=r"(r[2]), "=r"(r[3]) : "r"(a));
}
__device__ __forceinline__ void mma16816(float* c, const uint32_t* a,
                                         const uint32_t* b) {
    asm volatile(
        "mma.sync.aligned.m16n8k16.row.col.f32.f16.f16.f32 "
        "{%0,%1,%2,%3}, {%4,%5,%6,%7}, {%8,%9}, {%0,%1,%2,%3};"
        : "+f"(c[0]), "+f"(c[1]), "+f"(c[2]), "+f"(c[3])
        : "r"(a[0]), "r"(a[1]), "r"(a[2]), "r"(a[3]), "r"(b[0]), "r"(b[1]));
}

// ---------------------------------------------------------------------------
// GEMM: C[M,256] = A[M,256](fp16) @ B[256,256](fp16) + bias.  CTA 128x256,
// 8 warps 64x64, KC=32, 4-stage cp.async. blockIdx.y selects weight set.
// HOUT: store __half (attention operands) vs float (LN residual input).
// ---------------------------------------------------------------------------
template <bool HOUT>
__global__ __launch_bounds__(256, 1)
void hgemm2(const __half* __restrict__ Ap,
            const __half* B0, const __half* B1, const __half* B2,
            const float* bias0, const float* bias1, const float* bias2,
            void* C0, void* C1, void* C2) {
    extern __shared__ __align__(16) __half smh[];
    const int tid = threadIdx.x;
    const int bm = blockIdx.x * 128;
    const int wsel = blockIdx.y;
    const __half* Bp  = (wsel == 0) ? B0 : (wsel == 1) ? B1 : B2;
    const float*  bias = (wsel == 0) ? bias0 : (wsel == 1) ? bias1 : bias2;
    void*         C   = (wsel == 0) ? C0 : (wsel == 1) ? C1 : C2;
    const uint32_t sbase = smem_u32(smh);

    auto load_chunk = [&](int j, int s) {
        const uint32_t st = sbase + (uint32_t)(s * STG) * 2;
#pragma unroll
        for (int i = 0; i < 2; i++) {          // A: 512 16B segs
            int seg = tid + i * 256;
            int r = seg >> 2, c = seg & 3;
            cp16(st + (uint32_t)(r * LDA + c * 8) * 2,
                 Ap + (size_t)(bm + r) * KA + j * KC + c * 8);
        }
#pragma unroll
        for (int i = 0; i < 4; i++) {          // B: 1024 16B segs
            int seg = tid + i * 256;
            int r = seg >> 5, c = seg & 31;
            cp16(st + (uint32_t)(ASZ + r * LDB + c * 8) * 2,
                 Bp + (size_t)(j * KC + r) * Hn + c * 8);
        }
        cp_commit();
    };

    const int warp = tid >> 5, lane = tid & 31;
    const int wm = (warp & 1) * 64;
    const int wn = (warp >> 1) * 64;
    const int lr = lane & 15;
    const int lg8 = (lane >> 4) * 8;

    float acc[4][8][4];
#pragma unroll
    for (int mi = 0; mi < 4; mi++)
#pragma unroll
        for (int ni = 0; ni < 8; ni++)
#pragma unroll
            for (int k = 0; k < 4; k++) acc[mi][ni][k] = 0.f;

    load_chunk(0, 0);
    load_chunk(1, 1);
    load_chunk(2, 2);

    for (int j = 0; j < NC; j++) {
        asm volatile("cp.async.wait_group 2;" ::: "memory");
        __syncthreads();
        if (j + 3 < NC) load_chunk(j + 3, (j + 3) & 3);
        else            cp_commit();           // constant group depth

        const uint32_t st = sbase + (uint32_t)((j & 3) * STG) * 2;
#pragma unroll
        for (int ks = 0; ks < KC; ks += 16) {
            uint32_t a[4][4];
#pragma unroll
            for (int mi = 0; mi < 4; mi++)
                ldm_x4(a[mi], st + (uint32_t)((wm + mi * 16 + lr) * LDA + ks + lg8) * 2);
            uint32_t b[4][4];
#pragma unroll
            for (int np = 0; np < 4; np++)
                ldm_x4t(b[np], st + (uint32_t)(ASZ + (ks + lr) * LDB
                                               + wn + np * 16 + lg8) * 2);
#pragma unroll
            for (int mi = 0; mi < 4; mi++)
#pragma unroll
                for (int ni = 0; ni < 8; ni++)
                    mma16816(acc[mi][ni], a[mi], &b[ni >> 1][(ni & 1) * 2]);
        }
    }

    const int g = lane >> 2, tg = (lane & 3) * 2;
#pragma unroll
    for (int mi = 0; mi < 4; mi++) {
#pragma unroll
        for (int ni = 0; ni < 8; ni++) {
            int row = bm + wm + mi * 16 + g;
            int col = wn + ni * 8 + tg;
            float b0 = bias[col], b1 = bias[col + 1];
            float v00 = acc[mi][ni][0] + b0, v01 = acc[mi][ni][1] + b1;
            float v10 = acc[mi][ni][2] + b0, v11 = acc[mi][ni][3] + b1;
            if (HOUT) {
                __half* Ch = (__half*)C;
                *(__half2*)(Ch + (size_t)row * Hn + col) =
                    __floats2half2_rn(v00, v01);
                *(__half2*)(Ch + (size_t)(row + 8) * Hn + col) =
                    __floats2half2_rn(v10, v11);
            } else {
                float* Cf = (float*)C;
                *(float2*)(Cf + (size_t)row * Hn + col) = make_float2(v00, v01);
                *(float2*)(Cf + (size_t)(row + 8) * Hn + col) = make_float2(v10, v11);
            }
        }
    }
}

// ---------------------------------------------------------------------------
// weight prep: fp16(W) for the 4 sat weights
// ---------------------------------------------------------------------------
__global__ void wprep_kernel(const float* W0, const float* W1, const float* W2,
                             const float* W3) {
    const float* Ws[4] = {W0, W1, W2, W3};
    int wi = blockIdx.y;
    int k = blockIdx.x, n = threadIdx.x;
    g_BT[(size_t)wi * Hn * Hn + (size_t)k * Hn + n] =
        __float2half_rn(Ws[wi][(size_t)k * Hn + n]);
}

// x -> cur (fp32) + curP (fp16)
__global__ void splitcopy_kernel(const float* __restrict__ x) {
    int t = blockIdx.x * blockDim.x + threadIdx.x;   // Mn*Hn/8
    int row = t >> 5;
    int k0 = (t & 31) * 8;
    const float4* src = (const float4*)(x + (size_t)row * Hn + k0);
    float4* dst = (float4*)(g_cur + (size_t)row * Hn + k0);
    float4 v0 = src[0], v1 = src[1];
    dst[0] = v0; dst[1] = v1;
    __half hi[8];
    float vv[8] = {v0.x, v0.y, v0.z, v0.w, v1.x, v1.y, v1.z, v1.w};
#pragma unroll
    for (int j = 0; j < 8; j++) hi[j] = __float2half_rn(vv[j]);
    *(uint4*)(g_curP + (size_t)row * KA + k0) = *(uint4*)hi;
}

// partial column sums of x over L (stage 1 of mean)
__global__ void meanpart_kernel(const float* __restrict__ x) {
    int c = blockIdx.x, b = blockIdx.y, h = threadIdx.x;
    const float* p = x + ((size_t)b * Ln + c * 256) * Hn + h;
    float s = 0.f;
    for (int l = 0; l < 256; l++) s += p[(size_t)l * Hn];
    g_cpart[(b * 16 + c) * Hn + h] = s;
}

// ---------------------------------------------------------------------------
// center projections, 8-way k-split: grid (3*Bn, 8).
// sel: 0=Kcen(satWk) 1=Vcen(satWv) 2=Qrel(relWq). iter0 finishes the mean.
// ---------------------------------------------------------------------------
__global__ void proj_center_kernel(
    const float* __restrict__ satWk, const float* __restrict__ satbk,
    const float* __restrict__ satWv, const float* __restrict__ satbv,
    const float* __restrict__ relWq, const float* __restrict__ relbq,
    int use_cpart) {
    __shared__ float c[32];
    int b   = blockIdx.x % Bn;
    int sel = blockIdx.x / Bn;
    int ks  = blockIdx.y;
    int n   = threadIdx.x;
    int k0  = ks * 32;
    if (n < 32) {
        int k = k0 + n;
        float v;
        if (use_cpart) {
            float s = 0.f;
#pragma unroll
            for (int i = 0; i < 16; i++) s += g_cpart[(b * 16 + i) * Hn + k];
            v = s * (1.f / Ln);
            if (sel == 0) g_center[b * Hn + k] = v;
        } else {
            v = g_center[b * Hn + k];
        }
        c[n] = v;
    }
    __syncthreads();
    const float* W; const float* bi;
    switch (sel) {
        case 0: W = satWk; bi = satbk; break;
        case 1: W = satWv; bi = satbv; break;
        default: W = relWq; bi = relbq; break;
    }
    float s = 0.f;
#pragma unroll
    for (int k = 0; k < 32; k++) s += c[k] * W[(size_t)(k0 + k) * Hn + n];
    if (ks == 0) s += bi[n];
    g_cproj[ks][sel][b * Hn + n] = s;
}

// ---------------------------------------------------------------------------
// rel: w~_bh[k] = SCALE * sum_d Wrk[k][h*32+d] * qrel_bh[d]; s0 = center.w~
// ---------------------------------------------------------------------------
__global__ __launch_bounds__(256)
void rel_wtil_kernel(const float* __restrict__ relWk) {
    __shared__ float q[HDn];
    __shared__ float red[8];
    int bh = blockIdx.x;
    int b = bh >> 3, h = bh & 7;
    int t = threadIdx.x;
    if (t < HDn) {
        int i = b * Hn + h * HDn + t;
        float s = 0.f;
#pragma unroll
        for (int pp = 0; pp < 8; pp++) s += g_cproj[pp][2][i];
        q[t] = s;
    }
    __syncthreads();
    float w = 0.f;
#pragma unroll 8
    for (int d = 0; d < HDn; d++)
        w += relWk[(size_t)t * Hn + h * HDn + d] * q[d];
    w *= SCALE;
    g_wtil[bh * Hn + t] = w;

    // s0 = center . w~
    float c = g_center[b * Hn + t] * w;
#pragma unroll
    for (int off = 16; off; off >>= 1) c += __shfl_xor_sync(0xffffffffu, c, off);
    if ((t & 31) == 0) red[t >> 5] = c;
    __syncthreads();
    if (t == 0) {
        float tot = 0.f;
#pragma unroll
        for (int i = 0; i < 8; i++) tot += red[i];
        g_sc[bh * SCW] = tot;
    }
}

// ---------------------------------------------------------------------------
// satellite attention (fp16 operands) -> writes ctxP (fp16)
// ---------------------------------------------------------------------------
__global__ __launch_bounds__(256)
void sat_attn_kernel(const __half* __restrict__ Kc, const __half* __restrict__ Vc) {
    int token = blockIdx.x;
    int b = token >> 12;
    int l = token & (Ln - 1);
    int h = threadIdx.x >> 5;
    int d = threadIdx.x & 31;
    int col = h * HDn + d;

    size_t ic   = (size_t)token * Hn + col;
    int lb = (l + 1) & (Ln - 1);
    int la = (l == 0) ? (Ln - 1) : 0;
    size_t ibe  = ((size_t)(b * Ln + lb)) * Hn + col;
    size_t iaf  = ((size_t)(b * Ln + la)) * Hn + col;
    int icen = b * Hn + col;

    float kcen = 0.f, vcen = 0.f;
#pragma unroll
    for (int pp = 0; pp < 8; pp++) {
        kcen += g_cproj[pp][0][icen];
        vcen += g_cproj[pp][1][icen];
    }

    float q  = __half2float(g_Qh[ic]);
    float s0 = q * __half2float(Kc[ibe]);
    float s1 = q * __half2float(Kc[ic]);
    float s2 = q * __half2float(Kc[iaf]);
    float s3 = q * __half2float(g_Kxh[ic]);
    float s4 = q * kcen;
#pragma unroll
    for (int off = 16; off; off >>= 1) {
        s0 += __shfl_xor_sync(0xffffffffu, s0, off);
        s1 += __shfl_xor_sync(0xffffffffu, s1, off);
        s2 += __shfl_xor_sync(0xffffffffu, s2, off);
        s3 += __shfl_xor_sync(0xffffffffu, s3, off);
        s4 += __shfl_xor_sync(0xffffffffu, s4, off);
    }
    s0 *= SCALE; s1 *= SCALE; s2 *= SCALE; s3 *= SCALE; s4 *= SCALE;
    float mx = fmaxf(fmaxf(fmaxf(s0, s1), fmaxf(s2, s3)), s4);
    float e0 = expf(s0 - mx), e1 = expf(s1 - mx), e2 = expf(s2 - mx);
    float e3 = expf(s3 - mx), e4 = expf(s4 - mx);
    float inv = 1.f / (e0 + e1 + e2 + e3 + e4);
    float ctx = (e0 * __half2float(Vc[ibe]) + e1 * __half2float(Vc[ic]) +
                 e2 * __half2float(Vc[iaf]) + e3 * __half2float(g_Vxh[ic]) +
                 e4 * vcen) * inv;

    g_ctxP[(size_t)token * KA + col] = __float2half_rn(ctx);
}

// ---------------------------------------------------------------------------
// LN(relu(tmp + cur)) -> cur + curP + REL SCORES (8 heads per row).
// ---------------------------------------------------------------------------
__global__ __launch_bounds__(256)
void ln_rows_kernel(const float* __restrict__ tmp, float* __restrict__ cur,
                    float* __restrict__ dup,
                    const float* __restrict__ w, const float* __restrict__ bvec) {
    __shared__ float wts[8][Hn];     // 8 KB: w~ for this block's batch
    int warp = threadIdx.x >> 5;
    int lane = threadIdx.x & 31;
    int row = blockIdx.x * 8 + warp;
    int b = row >> 12;
    int l = row & (Ln - 1);
    int k0 = lane * 8;
    size_t base = (size_t)row * Hn + k0;

    for (int i = threadIdx.x; i < 8 * Hn; i += 256)
        wts[i >> 8][i & 255] = g_wtil[(b * 8 + (i >> 8)) * Hn + (i & 255)];
    __syncthreads();

    float4 t0 = *(const float4*)(tmp + base);
    float4 t1 = *(const float4*)(tmp + base + 4);
    float4 c0 = *(const float4*)(cur + base);
    float4 c1 = *(const float4*)(cur + base + 4);
    float v[8] = { fmaxf(t0.x + c0.x, 0.f), fmaxf(t0.y + c0.y, 0.f),
                   fmaxf(t0.z + c0.z, 0.f), fmaxf(t0.w + c0.w, 0.f),
                   fmaxf(t1.x + c1.x, 0.f), fmaxf(t1.y + c1.y, 0.f),
                   fmaxf(t1.z + c1.z, 0.f), fmaxf(t1.w + c1.w, 0.f) };

    float s = 0.f;
#pragma unroll
    for (int j = 0; j < 8; j++) s += v[j];
#pragma unroll
    for (int off = 16; off; off >>= 1) s += __shfl_xor_sync(0xffffffffu, s, off);
    float mean = s * (1.f / Hn);

    float s2 = 0.f;
#pragma unroll
    for (int j = 0; j < 8; j++) { float d = v[j] - mean; s2 += d * d; }
#pragma unroll
    for (int off = 16; off; off >>= 1) s2 += __shfl_xor_sync(0xffffffffu, s2, off);
    float rstd = rsqrtf(s2 * (1.f / Hn) + LNEPS);

    float4 w0 = *(const float4*)(w + k0);
    float4 w1 = *(const float4*)(w + k0 + 4);
    float4 b0 = *(const float4*)(bvec + k0);
    float4 b1 = *(const float4*)(bvec + k0 + 4);
    float ww[8] = {w0.x, w0.y, w0.z, w0.w, w1.x, w1.y, w1.z, w1.w};
    float bb[8] = {b0.x, b0.y, b0.z, b0.w, b1.x, b1.y, b1.z, b1.w};

    float o[8];
    __half hi[8];
#pragma unroll
    for (int j = 0; j < 8; j++) {
        o[j] = ww[j] * (v[j] - mean) * rstd + bb[j];
        hi[j] = __float2half_rn(o[j]);
    }
    float4 oo0 = make_float4(o[0], o[1], o[2], o[3]);
    float4 oo1 = make_float4(o[4], o[5], o[6], o[7]);
    *(float4*)(cur + base)     = oo0;
    *(float4*)(cur + base + 4) = oo1;
    if (dup) {
        *(float4*)(dup + base)     = oo0;
        *(float4*)(dup + base + 4) = oo1;
    }
    *(uint4*)(g_curP + (size_t)row * KA + k0) = *(uint4*)hi;

    // rel scores: s_h = row . w~_h  (new cur row still in registers)
#pragma unroll
    for (int h = 0; h < 8; h++) {
        float p = 0.f;
#pragma unroll
        for (int j = 0; j < 8; j++) p += o[j] * wts[h][k0 + j];
#pragma unroll
        for (int off = 16; off; off >>= 1)
            p += __shfl_xor_sync(0xffffffffu, p, off);
        if (lane == 0)
            g_sc[(b * 8 + h) * SCW + 1 + l] = p;
    }
}

// ---------------------------------------------------------------------------
// rel softmax stats: per bh, max + sum-exp over 4097 scores
// ---------------------------------------------------------------------------
__global__ __launch_bounds__(256)
void rel_stat_kernel() {
    __shared__ float red[8];
    int bh = blockIdx.x;
    int t = threadIdx.x;
    const float* sc = g_sc + bh * SCW;

    float m = -1e30f;
    for (int j = t; j <= Ln; j += 256) m = fmaxf(m, sc[j]);
#pragma unroll
    for (int off = 16; off; off >>= 1)
        m = fmaxf(m, __shfl_xor_sync(0xffffffffu, m, off));
    if ((t & 31) == 0) red[t >> 5] = m;
    __syncthreads();
    float mm = -1e30f;
#pragma unroll
    for (int i = 0; i < 8; i++) mm = fmaxf(mm, red[i]);
    __syncthreads();

    float z = 0.f;
    for (int j = t; j <= Ln; j += 256) z += expf(sc[j] - mm);
#pragma unroll
    for (int off = 16; off; off >>= 1) z += __shfl_xor_sync(0xffffffffu, z, off);
    if ((t & 31) == 0) red[t >> 5] = z;
    __syncthreads();
    if (t == 0) {
        float tot = 0.f;
#pragma unroll
        for (int i = 0; i < 8; i++) tot += red[i];
        g_pm[bh] = mm;
        g_ps[bh] = tot;
    }
}

// ---------------------------------------------------------------------------
// rel weighted row-sum: grid (Bn, NSP=32); 128 keys per chunk.
// ---------------------------------------------------------------------------
__global__ __launch_bounds__(256)
void rel_wsum_kernel() {
    __shared__ float p[8][128];
    __shared__ float mz[16];
    int b = blockIdx.x, sp = blockIdx.y;
    int t = threadIdx.x;
    if (t < 8)       mz[t] = g_pm[b * 8 + t];
    else if (t < 16) mz[t] = 1.f / g_ps[b * 8 + (t - 8)];
    __syncthreads();
    for (int i = t; i < 8 * 128; i += 256) {
        int hh = i >> 7, jj = i & 127;
        p[hh][jj] = expf(g_sc[(b * 8 + hh) * SCW + 1 + sp * 128 + jj] - mz[hh])
                    * mz[8 + hh];
    }
    __syncthreads();

    int h = t >> 5, kg = t & 31;
    float a0x = 0.f, a0y = 0.f, a0z = 0.f, a0w = 0.f;
    float a1x = 0.f, a1y = 0.f, a1z = 0.f, a1w = 0.f;
    for (int jj = 0; jj < 128; jj++) {
        size_t row = (size_t)(b * Ln + sp * 128 + jj) * Hn + kg * 8;
        float4 c0 = *(const float4*)(g_cur + row);
        float4 c1 = *(const float4*)(g_cur + row + 4);
        float pp = p[h][jj];
        a0x += pp * c0.x; a0y += pp * c0.y; a0z += pp * c0.z; a0w += pp * c0.w;
        a1x += pp * c1.x; a1y += pp * c1.y; a1z += pp * c1.z; a1w += pp * c1.w;
    }
    size_t o = (size_t)((b * NSP + sp) * 8 + h) * Hn + kg * 8;
    *(float4*)(g_upart + o)     = make_float4(a0x, a0y, a0z, a0w);
    *(float4*)(g_upart + o + 4) = make_float4(a1x, a1y, a1z, a1w);
}

// ---------------------------------------------------------------------------
// rel epilogue: u = sum_sp upart + p0*center; cx = u@Wrv + bv;
// dst = LN(relu(cx@Wo + bo + center)); also updates g_center
// ---------------------------------------------------------------------------
__global__ __launch_bounds__(256)
void rel_epi_kernel(const float* __restrict__ Wrv, const float* __restrict__ brv,
                    const float* __restrict__ Wo, const float* __restrict__ bo,
                    const float* __restrict__ lnw, const float* __restrict__ lnb,
                    float* __restrict__ dst) {
    __shared__ float u[8][Hn];
    __shared__ float cx[Hn];
    __shared__ float red[8];
    int b = blockIdx.x;
    int n = threadIdx.x;

    float ctr = g_center[b * Hn + n];
#pragma unroll
    for (int h = 0; h < 8; h++) {
        float s = 0.f;
        for (int sp = 0; sp < NSP; sp++)
            s += g_upart[(size_t)((b * NSP + sp) * 8 + h) * Hn + n];
        float p0 = expf(g_sc[(b * 8 + h) * SCW] - g_pm[b * 8 + h]) / g_ps[b * 8 + h];
        u[h][n] = s + p0 * ctr;
    }
    __syncthreads();

    int h = n >> 5;
    float cval = 0.f;
#pragma unroll 8
    for (int k = 0; k < Hn; k++) cval += u[h][k] * Wrv[(size_t)k * Hn + n];
    cx[n] = cval + brv[n];
    __syncthreads();

    float s = 0.f;
#pragma unroll 8
    for (int k = 0; k < Hn; k++) s += cx[k] * Wo[(size_t)k * Hn + n];
    float v = fmaxf(s + bo[n] + ctr, 0.f);

    float r = v;
#pragma unroll
    for (int off = 16; off; off >>= 1) r += __shfl_xor_sync(0xffffffffu, r, off);
    if ((n & 31) == 0) red[n >> 5] = r;
    __syncthreads();
    float tot = 0.f;
#pragma unroll
    for (int i = 0; i < 8; i++) tot += red[i];
    float mean = tot * (1.f / Hn);
    __syncthreads();

    float dv = v - mean;
    float r2 = dv * dv;
#pragma unroll
    for (int off = 16; off; off >>= 1) r2 += __shfl_xor_sync(0xffffffffu, r2, off);
    if ((n & 31) == 0) red[n >> 5] = r2;
    __syncthreads();
    tot = 0.f;
#pragma unroll
    for (int i = 0; i < 8; i++) tot += red[i];
    float var = tot * (1.f / Hn);

    float o = lnw[n] * dv * rsqrtf(var + LNEPS) + lnb[n];
    g_center[b * Hn + n] = o;
    dst[b * Hn + n] = o;
}

// ---------------------------------------------------------------------------
extern "C" void kernel_launch(void* const* d_in, const int* in_sizes, int n_in,
                              void* d_out, int out_size) {
    const float* x     = (const float*)d_in[0];
    const float* satWq = (const float*)d_in[1];  const float* satbq = (const float*)d_in[2];
    const float* satWk = (const float*)d_in[3];  const float* satbk = (const float*)d_in[4];
    const float* satWv = (const float*)d_in[5];  const float* satbv = (const float*)d_in[6];
    const float* satWo = (const float*)d_in[7];  const float* satbo = (const float*)d_in[8];
    const float* relWq = (const float*)d_in[9];  const float* relbq = (const float*)d_in[10];
    const float* relWk = (const float*)d_in[11]; const float* relbk = (const float*)d_in[12];
    const float* relWv = (const float*)d_in[13]; const float* relbv = (const float*)d_in[14];
    const float* relWo = (const float*)d_in[15]; const float* relbo = (const float*)d_in[16];
    const float* slnw  = (const float*)d_in[17]; const float* slnb  = (const float*)d_in[18];
    const float* rlnw  = (const float*)d_in[19]; const float* rlnb  = (const float*)d_in[20];
    float* out = (float*)d_out;
    (void)relbk;   // key bias cancels in softmax

    float *cur, *tmp, *center;
    __half *curP, *ctxP, *BT, *Qh, *Kch, *Vch, *Kxh, *Vxh;
    cudaGetSymbolAddress((void**)&cur,  g_cur);
    cudaGetSymbolAddress((void**)&tmp,  g_tmp);
    cudaGetSymbolAddress((void**)&curP, g_curP);
    cudaGetSymbolAddress((void**)&ctxP, g_ctxP);
    cudaGetSymbolAddress((void**)&BT,   g_BT);
    cudaGetSymbolAddress((void**)&center, g_center);
    cudaGetSymbolAddress((void**)&Qh,  g_Qh);
    cudaGetSymbolAddress((void**)&Kch, g_Kch);
    cudaGetSymbolAddress((void**)&Vch, g_Vch);
    cudaGetSymbolAddress((void**)&Kxh, g_Kxh);
    cudaGetSymbolAddress((void**)&Vxh, g_Vxh);

    cudaFuncSetAttribute(hgemm2<true>, cudaFuncAttributeMaxDynamicSharedMemorySize,
                         GEMM_SMEM);
    cudaFuncSetAttribute(hgemm2<false>, cudaFuncAttributeMaxDynamicSharedMemorySize,
                         GEMM_SMEM);

    // fp16 weights: 0 satWq, 1 satWk, 2 satWv, 3 satWo
    wprep_kernel<<<dim3(Hn, 4), Hn>>>(satWq, satWk, satWv, satWo);

    splitcopy_kernel<<<Mn * Hn / 8 / 256, 256>>>(x);
    meanpart_kernel<<<dim3(16, Bn), Hn>>>(x);

    const __half* Wq = BT + (size_t)0 * Hn * Hn;
    const __half* Wk = BT + (size_t)1 * Hn * Hn;
    const __half* Wv = BT + (size_t)2 * Hn * Hn;
    const __half* Wo = BT + (size_t)3 * Hn * Hn;

    for (int it = 0; it < 2; it++) {
        proj_center_kernel<<<dim3(3 * Bn, 8), Hn>>>(
            satWk, satbk, satWv, satbv, relWq, relbq, it == 0 ? 1 : 0);
        rel_wtil_kernel<<<Bn * NHn, Hn>>>(relWk);   // before GEMMs: ln_rows needs w~
        // iter 0: cur == x, so K/V projections double as loop-invariant Kx/Vx
        __half* Kdst = (it == 0) ? Kxh : Kch;
        __half* Vdst = (it == 0) ? Vxh : Vch;
        hgemm2<true><<<dim3(Mn / 128, 3), 256, GEMM_SMEM>>>(
            curP, Wq, Wk, Wv, satbq, satbk, satbv, Qh, Kdst, Vdst);
        sat_attn_kernel<<<Mn, 256>>>(Kdst, Vdst);
        hgemm2<false><<<dim3(Mn / 128, 1), 256, GEMM_SMEM>>>(
            ctxP, Wo, Wo, Wo, satbo, satbo, satbo, tmp, tmp, tmp);
        float* dup = (it == 0) ? (float*)nullptr : out;
        ln_rows_kernel<<<Mn / 8, 256>>>(tmp, cur, dup, slnw, slnb);

        rel_stat_kernel<<<Bn * NHn, 256>>>();
        rel_wsum_kernel<<<dim3(Bn, NSP), 256>>>();
        float* cdst = (it == 0) ? center : (out + (size_t)Mn * Hn);
        rel_epi_kernel<<<Bn, Hn>>>(relWv, relbv, relWo, relbo, rlnw, rlnb, cdst);
    }
}

// round 13
// speedup vs baseline: 1.4200x; 1.4200x over previous
#include <cuda_runtime.h>
#include <cuda_fp16.h>
#include <math.h>
#include <stdint.h>

// ---------------------------------------------------------------------------
// StarTransformerLayer, GB300 (compute_103 -> mma.sync path).
// B=8, L=4096, H=256, NH=8, HD=32, 2 iterations.
// Sat GEMMs: fp16 in / fp32 accum (error calibrated ~5e-4 < 1e-3).
// Rel attention: GEMM-free; scores fused into ln_rows; wsum split 32 ways.
// R13 = exact revert to the best-known R11 configuration (632.9 us):
// controlled experiment after the unexplained R12 regression (fp16 attention
// operands, -traffic, +41% time -> suspect DVFS/node throttle; see journal).
// ---------------------------------------------------------------------------

namespace {
constexpr int Bn  = 8;
constexpr int Ln  = 4096;
constexpr int Hn  = 256;
constexpr int NHn = 8;
constexpr int HDn = 32;
constexpr int Mn  = Bn * Ln;          // 32768
constexpr int KA  = 256;              // fp16 A columns
constexpr int SCW = 4128;             // score row stride (4097 used)
constexpr int NSP = 32;               // wsum chunks (128 keys each)
constexpr float SCALE = 0.17677669529663688f;   // 1/sqrt(32)
constexpr float LNEPS = 1e-12f;
// GEMM tiling
constexpr int KC   = 32;
constexpr int NC   = KA / KC;         // 8 chunks
constexpr int LDA  = 40;              // 32 + 8 pad (halfs)
constexpr int LDB  = 264;             // 256 + 8 pad (halfs)
constexpr int ASZ  = 128 * LDA;       // 5120 halfs
constexpr int BSZ  = KC * LDB;        // 8448 halfs
constexpr int STG  = ASZ + BSZ;       // 13568 halfs
constexpr int GEMM_SMEM = STG * 2 * 4;   // 108544 bytes (4 stages)
}

// ---- scratch (device globals) ---------------------------------------------
__device__ float  g_cur [Mn * Hn];
__device__ __align__(16) __half g_curP[(size_t)Mn * KA];
__device__ __align__(16) __half g_ctxP[(size_t)Mn * KA];
__device__ __align__(16) __half g_BT  [4 * (size_t)Hn * Hn];
__device__ float  g_Q   [Mn * Hn];
__device__ float  g_Kc  [Mn * Hn];
__device__ float  g_Vc  [Mn * Hn];
__device__ float  g_Kx  [Mn * Hn];
__device__ float  g_Vx  [Mn * Hn];
__device__ float  g_tmp [Mn * Hn];

__device__ float g_center[Bn * Hn];
// center projections, 8 k-partials: [ks][sel][b*Hn+n]; sel 0=Kcen 1=Vcen 2=Qrel
__device__ float g_cproj[8][3][Bn * Hn];
__device__ float g_cpart[Bn * 16 * Hn];

// rel attention scratch
__device__ float g_wtil[64 * Hn];            // per (b,h): w~ (includes SCALE)
__device__ float g_sc  [64 * SCW];           // scores, jidx 0..4096
__device__ float g_pm  [64];                 // per-bh max
__device__ float g_ps  [64];                 // per-bh sum-exp
__device__ float g_upart[(size_t)Bn * NSP * NHn * Hn];   // partial wsums

// ---------------------------------------------------------------------------
// helpers
// ---------------------------------------------------------------------------
__device__ __forceinline__ uint32_t smem_u32(const void* p) {
    uint32_t a;
    asm("{ .reg .u64 t; cvta.to.shared.u64 t, %1; cvt.u32.u64 %0, t; }"
        : "=r"(a) : "l"(p));
    return a;
}
__device__ __forceinline__ void cp16(uint32_t s, const void* g) {
    asm volatile("cp.async.cg.shared.global [%0], [%1], 16;" :: "r"(s), "l"(g));
}
__device__ __forceinline__ void cp_commit() {
    asm volatile("cp.async.commit_group;" ::: "memory");
}
__device__ __forceinline__ void ldm_x4(uint32_t* r, uint32_t a) {
    asm volatile("ldmatrix.sync.aligned.m8n8.x4.shared.b16 {%0,%1,%2,%3}, [%4];"
                 : "=r"(r[0]), "=r"(r[1]), "=r"(r[2]), "=r"(r[3]) : "r"(a));
}
__device__ __forceinline__ void ldm_x4t(uint32_t* r, uint32_t a) {
    asm volatile("ldmatrix.sync.aligned.m8n8.x4.trans.shared.b16 {%0,%1,%2,%3}, [%4];"
                 : "=r"(r[0]), "=r"(r[1]), "=r"(r[2]), "=r"(r[3]) : "r"(a));
}
__device__ __forceinline__ void mma16816(float* c, const uint32_t* a,
                                         const uint32_t* b) {
    asm volatile(
        "mma.sync.aligned.m16n8k16.row.col.f32.f16.f16.f32 "
        "{%0,%1,%2,%3}, {%4,%5,%6,%7}, {%8,%9}, {%0,%1,%2,%3};"
        : "+f"(c[0]), "+f"(c[1]), "+f"(c[2]), "+f"(c[3])
        : "r"(a[0]), "r"(a[1]), "r"(a[2]), "r"(a[3]), "r"(b[0]), "r"(b[1]));
}

// ---------------------------------------------------------------------------
// GEMM: C[M,256] = A[M,256](fp16) @ B[256,256](fp16) + bias.  CTA 128x256,
// 8 warps 64x64, KC=32, 4-stage cp.async. blockIdx.y selects weight set.
// ---------------------------------------------------------------------------
__global__ __launch_bounds__(256, 1)
void hgemm2(const __half* __restrict__ Ap,
            const __half* B0, const __half* B1, const __half* B2,
            const float* bias0, const float* bias1, const float* bias2,
            float* C0, float* C1, float* C2) {
    extern __shared__ __align__(16) __half smh[];
    const int tid = threadIdx.x;
    const int bm = blockIdx.x * 128;
    const int wsel = blockIdx.y;
    const __half* Bp  = (wsel == 0) ? B0 : (wsel == 1) ? B1 : B2;
    const float*  bias = (wsel == 0) ? bias0 : (wsel == 1) ? bias1 : bias2;
    float*        C   = (wsel == 0) ? C0 : (wsel == 1) ? C1 : C2;
    const uint32_t sbase = smem_u32(smh);

    auto load_chunk = [&](int j, int s) {
        const uint32_t st = sbase + (uint32_t)(s * STG) * 2;
#pragma unroll
        for (int i = 0; i < 2; i++) {          // A: 512 16B segs
            int seg = tid + i * 256;
            int r = seg >> 2, c = seg & 3;
            cp16(st + (uint32_t)(r * LDA + c * 8) * 2,
                 Ap + (size_t)(bm + r) * KA + j * KC + c * 8);
        }
#pragma unroll
        for (int i = 0; i < 4; i++) {          // B: 1024 16B segs
            int seg = tid + i * 256;
            int r = seg >> 5, c = seg & 31;
            cp16(st + (uint32_t)(ASZ + r * LDB + c * 8) * 2,
                 Bp + (size_t)(j * KC + r) * Hn + c * 8);
        }
        cp_commit();
    };

    const int warp = tid >> 5, lane = tid & 31;
    const int wm = (warp & 1) * 64;
    const int wn = (warp >> 1) * 64;
    const int lr = lane & 15;
    const int lg8 = (lane >> 4) * 8;

    float acc[4][8][4];
#pragma unroll
    for (int mi = 0; mi < 4; mi++)
#pragma unroll
        for (int ni = 0; ni < 8; ni++)
#pragma unroll
            for (int k = 0; k < 4; k++) acc[mi][ni][k] = 0.f;

    load_chunk(0, 0);
    load_chunk(1, 1);
    load_chunk(2, 2);

    for (int j = 0; j < NC; j++) {
        asm volatile("cp.async.wait_group 2;" ::: "memory");
        __syncthreads();
        if (j + 3 < NC) load_chunk(j + 3, (j + 3) & 3);
        else            cp_commit();           // constant group depth

        const uint32_t st = sbase + (uint32_t)((j & 3) * STG) * 2;
#pragma unroll
        for (int ks = 0; ks < KC; ks += 16) {
            uint32_t a[4][4];
#pragma unroll
            for (int mi = 0; mi < 4; mi++)
                ldm_x4(a[mi], st + (uint32_t)((wm + mi * 16 + lr) * LDA + ks + lg8) * 2);
            uint32_t b[4][4];
#pragma unroll
            for (int np = 0; np < 4; np++)
                ldm_x4t(b[np], st + (uint32_t)(ASZ + (ks + lr) * LDB
                                               + wn + np * 16 + lg8) * 2);
#pragma unroll
            for (int mi = 0; mi < 4; mi++)
#pragma unroll
                for (int ni = 0; ni < 8; ni++)
                    mma16816(acc[mi][ni], a[mi], &b[ni >> 1][(ni & 1) * 2]);
        }
    }

    const int g = lane >> 2, tg = (lane & 3) * 2;
#pragma unroll
    for (int mi = 0; mi < 4; mi++) {
#pragma unroll
        for (int ni = 0; ni < 8; ni++) {
            int row = bm + wm + mi * 16 + g;
            int col = wn + ni * 8 + tg;
            float b0 = bias[col], b1 = bias[col + 1];
            float2 o0 = { acc[mi][ni][0] + b0, acc[mi][ni][1] + b1 };
            float2 o1 = { acc[mi][ni][2] + b0, acc[mi][ni][3] + b1 };
            *(float2*)(C + (size_t)row * Hn + col) = o0;
            *(float2*)(C + (size_t)(row + 8) * Hn + col) = o1;
        }
    }
}

// ---------------------------------------------------------------------------
// weight prep: fp16(W) for the 4 sat weights
// ---------------------------------------------------------------------------
__global__ void wprep_kernel(const float* W0, const float* W1, const float* W2,
                             const float* W3) {
    const float* Ws[4] = {W0, W1, W2, W3};
    int wi = blockIdx.y;
    int k = blockIdx.x, n = threadIdx.x;
    g_BT[(size_t)wi * Hn * Hn + (size_t)k * Hn + n] =
        __float2half_rn(Ws[wi][(size_t)k * Hn + n]);
}

// x -> cur (fp32) + curP (fp16)
__global__ void splitcopy_kernel(const float* __restrict__ x) {
    int t = blockIdx.x * blockDim.x + threadIdx.x;   // Mn*Hn/8
    int row = t >> 5;
    int k0 = (t & 31) * 8;
    const float4* src = (const float4*)(x + (size_t)row * Hn + k0);
    float4* dst = (float4*)(g_cur + (size_t)row * Hn + k0);
    float4 v0 = src[0], v1 = src[1];
    dst[0] = v0; dst[1] = v1;
    __half hi[8];
    float vv[8] = {v0.x, v0.y, v0.z, v0.w, v1.x, v1.y, v1.z, v1.w};
#pragma unroll
    for (int j = 0; j < 8; j++) hi[j] = __float2half_rn(vv[j]);
    *(uint4*)(g_curP + (size_t)row * KA + k0) = *(uint4*)hi;
}

// partial column sums of x over L (stage 1 of mean)
__global__ void meanpart_kernel(const float* __restrict__ x) {
    int c = blockIdx.x, b = blockIdx.y, h = threadIdx.x;
    const float* p = x + ((size_t)b * Ln + c * 256) * Hn + h;
    float s = 0.f;
    for (int l = 0; l < 256; l++) s += p[(size_t)l * Hn];
    g_cpart[(b * 16 + c) * Hn + h] = s;
}

// ---------------------------------------------------------------------------
// center projections, 8-way k-split: grid (3*Bn, 8).
// sel: 0=Kcen(satWk) 1=Vcen(satWv) 2=Qrel(relWq). iter0 finishes the mean.
// ---------------------------------------------------------------------------
__global__ void proj_center_kernel(
    const float* __restrict__ satWk, const float* __restrict__ satbk,
    const float* __restrict__ satWv, const float* __restrict__ satbv,
    const float* __restrict__ relWq, const float* __restrict__ relbq,
    int use_cpart) {
    __shared__ float c[32];
    int b   = blockIdx.x % Bn;
    int sel = blockIdx.x / Bn;
    int ks  = blockIdx.y;
    int n   = threadIdx.x;
    int k0  = ks * 32;
    if (n < 32) {
        int k = k0 + n;
        float v;
        if (use_cpart) {
            float s = 0.f;
#pragma unroll
            for (int i = 0; i < 16; i++) s += g_cpart[(b * 16 + i) * Hn + k];
            v = s * (1.f / Ln);
            if (sel == 0) g_center[b * Hn + k] = v;
        } else {
            v = g_center[b * Hn + k];
        }
        c[n] = v;
    }
    __syncthreads();
    const float* W; const float* bi;
    switch (sel) {
        case 0: W = satWk; bi = satbk; break;
        case 1: W = satWv; bi = satbv; break;
        default: W = relWq; bi = relbq; break;
    }
    float s = 0.f;
#pragma unroll
    for (int k = 0; k < 32; k++) s += c[k] * W[(size_t)(k0 + k) * Hn + n];
    if (ks == 0) s += bi[n];
    g_cproj[ks][sel][b * Hn + n] = s;
}

// ---------------------------------------------------------------------------
// rel: w~_bh[k] = SCALE * sum_d Wrk[k][h*32+d] * qrel_bh[d]; s0 = center.w~
// (runs right after proj_center, BEFORE the GEMMs — ln_rows consumes w~)
// ---------------------------------------------------------------------------
__global__ __launch_bounds__(256)
void rel_wtil_kernel(const float* __restrict__ relWk) {
    __shared__ float q[HDn];
    __shared__ float red[8];
    int bh = blockIdx.x;
    int b = bh >> 3, h = bh & 7;
    int t = threadIdx.x;
    if (t < HDn) {
        int i = b * Hn + h * HDn + t;
        float s = 0.f;
#pragma unroll
        for (int pp = 0; pp < 8; pp++) s += g_cproj[pp][2][i];
        q[t] = s;
    }
    __syncthreads();
    float w = 0.f;
#pragma unroll 8
    for (int d = 0; d < HDn; d++)
        w += relWk[(size_t)t * Hn + h * HDn + d] * q[d];
    w *= SCALE;
    g_wtil[bh * Hn + t] = w;

    // s0 = center . w~
    float c = g_center[b * Hn + t] * w;
#pragma unroll
    for (int off = 16; off; off >>= 1) c += __shfl_xor_sync(0xffffffffu, c, off);
    if ((t & 31) == 0) red[t >> 5] = c;
    __syncthreads();
    if (t == 0) {
        float tot = 0.f;
#pragma unroll
        for (int i = 0; i < 8; i++) tot += red[i];
        g_sc[bh * SCW] = tot;
    }
}

// ---------------------------------------------------------------------------
// satellite attention -> writes ctxP (fp16)
// ---------------------------------------------------------------------------
__global__ __launch_bounds__(256)
void sat_attn_kernel(const float* __restrict__ Kc, const float* __restrict__ Vc) {
    int token = blockIdx.x;
    int b = token >> 12;
    int l = token & (Ln - 1);
    int h = threadIdx.x >> 5;
    int d = threadIdx.x & 31;
    int col = h * HDn + d;

    size_t ic   = (size_t)token * Hn + col;
    int lb = (l + 1) & (Ln - 1);
    int la = (l == 0) ? (Ln - 1) : 0;
    size_t ibe  = ((size_t)(b * Ln + lb)) * Hn + col;
    size_t iaf  = ((size_t)(b * Ln + la)) * Hn + col;
    int icen = b * Hn + col;

    float kcen = 0.f, vcen = 0.f;
#pragma unroll
    for (int pp = 0; pp < 8; pp++) {
        kcen += g_cproj[pp][0][icen];
        vcen += g_cproj[pp][1][icen];
    }

    float q  = g_Q[ic];
    float s0 = q * Kc[ibe];
    float s1 = q * Kc[ic];
    float s2 = q * Kc[iaf];
    float s3 = q * g_Kx[ic];
    float s4 = q * kcen;
#pragma unroll
    for (int off = 16; off; off >>= 1) {
        s0 += __shfl_xor_sync(0xffffffffu, s0, off);
        s1 += __shfl_xor_sync(0xffffffffu, s1, off);
        s2 += __shfl_xor_sync(0xffffffffu, s2, off);
        s3 += __shfl_xor_sync(0xffffffffu, s3, off);
        s4 += __shfl_xor_sync(0xffffffffu, s4, off);
    }
    s0 *= SCALE; s1 *= SCALE; s2 *= SCALE; s3 *= SCALE; s4 *= SCALE;
    float mx = fmaxf(fmaxf(fmaxf(s0, s1), fmaxf(s2, s3)), s4);
    float e0 = expf(s0 - mx), e1 = expf(s1 - mx), e2 = expf(s2 - mx);
    float e3 = expf(s3 - mx), e4 = expf(s4 - mx);
    float inv = 1.f / (e0 + e1 + e2 + e3 + e4);
    float ctx = (e0 * Vc[ibe] + e1 * Vc[ic] + e2 * Vc[iaf] +
                 e3 * g_Vx[ic] + e4 * vcen) * inv;

    g_ctxP[(size_t)token * KA + col] = __float2half_rn(ctx);
}

// ---------------------------------------------------------------------------
// LN(relu(tmp + cur)) -> cur + curP + REL SCORES (8 heads per row).
// Warp per row; w~ staged in smem (one batch per block: 8 rows, same b).
// ---------------------------------------------------------------------------
__global__ __launch_bounds__(256)
void ln_rows_kernel(const float* __restrict__ tmp, float* __restrict__ cur,
                    float* __restrict__ dup,
                    const float* __restrict__ w, const float* __restrict__ bvec) {
    __shared__ float wts[8][Hn];     // 8 KB: w~ for this block's batch
    int warp = threadIdx.x >> 5;
    int lane = threadIdx.x & 31;
    int row = blockIdx.x * 8 + warp;
    int b = row >> 12;
    int l = row & (Ln - 1);
    int k0 = lane * 8;
    size_t base = (size_t)row * Hn + k0;

    for (int i = threadIdx.x; i < 8 * Hn; i += 256)
        wts[i >> 8][i & 255] = g_wtil[(b * 8 + (i >> 8)) * Hn + (i & 255)];
    __syncthreads();

    float4 t0 = *(const float4*)(tmp + base);
    float4 t1 = *(const float4*)(tmp + base + 4);
    float4 c0 = *(const float4*)(cur + base);
    float4 c1 = *(const float4*)(cur + base + 4);
    float v[8] = { fmaxf(t0.x + c0.x, 0.f), fmaxf(t0.y + c0.y, 0.f),
                   fmaxf(t0.z + c0.z, 0.f), fmaxf(t0.w + c0.w, 0.f),
                   fmaxf(t1.x + c1.x, 0.f), fmaxf(t1.y + c1.y, 0.f),
                   fmaxf(t1.z + c1.z, 0.f), fmaxf(t1.w + c1.w, 0.f) };

    float s = 0.f;
#pragma unroll
    for (int j = 0; j < 8; j++) s += v[j];
#pragma unroll
    for (int off = 16; off; off >>= 1) s += __shfl_xor_sync(0xffffffffu, s, off);
    float mean = s * (1.f / Hn);

    float s2 = 0.f;
#pragma unroll
    for (int j = 0; j < 8; j++) { float d = v[j] - mean; s2 += d * d; }
#pragma unroll
    for (int off = 16; off; off >>= 1) s2 += __shfl_xor_sync(0xffffffffu, s2, off);
    float rstd = rsqrtf(s2 * (1.f / Hn) + LNEPS);

    float4 w0 = *(const float4*)(w + k0);
    float4 w1 = *(const float4*)(w + k0 + 4);
    float4 b0 = *(const float4*)(bvec + k0);
    float4 b1 = *(const float4*)(bvec + k0 + 4);
    float ww[8] = {w0.x, w0.y, w0.z, w0.w, w1.x, w1.y, w1.z, w1.w};
    float bb[8] = {b0.x, b0.y, b0.z, b0.w, b1.x, b1.y, b1.z, b1.w};

    float o[8];
    __half hi[8];
#pragma unroll
    for (int j = 0; j < 8; j++) {
        o[j] = ww[j] * (v[j] - mean) * rstd + bb[j];
        hi[j] = __float2half_rn(o[j]);
    }
    float4 oo0 = make_float4(o[0], o[1], o[2], o[3]);
    float4 oo1 = make_float4(o[4], o[5], o[6], o[7]);
    *(float4*)(cur + base)     = oo0;
    *(float4*)(cur + base + 4) = oo1;
    if (dup) {
        *(float4*)(dup + base)     = oo0;
        *(float4*)(dup + base + 4) = oo1;
    }
    *(uint4*)(g_curP + (size_t)row * KA + k0) = *(uint4*)hi;

    // rel scores: s_h = row . w~_h  (new cur row still in registers)
#pragma unroll
    for (int h = 0; h < 8; h++) {
        float p = 0.f;
#pragma unroll
        for (int j = 0; j < 8; j++) p += o[j] * wts[h][k0 + j];
#pragma unroll
        for (int off = 16; off; off >>= 1)
            p += __shfl_xor_sync(0xffffffffu, p, off);
        if (lane == 0)
            g_sc[(b * 8 + h) * SCW + 1 + l] = p;
    }
}

// ---------------------------------------------------------------------------
// rel softmax stats: per bh, max + sum-exp over 4097 scores
// ---------------------------------------------------------------------------
__global__ __launch_bounds__(256)
void rel_stat_kernel() {
    __shared__ float red[8];
    int bh = blockIdx.x;
    int t = threadIdx.x;
    const float* sc = g_sc + bh * SCW;

    float m = -1e30f;
    for (int j = t; j <= Ln; j += 256) m = fmaxf(m, sc[j]);
#pragma unroll
    for (int off = 16; off; off >>= 1)
        m = fmaxf(m, __shfl_xor_sync(0xffffffffu, m, off));
    if ((t & 31) == 0) red[t >> 5] = m;
    __syncthreads();
    float mm = -1e30f;
#pragma unroll
    for (int i = 0; i < 8; i++) mm = fmaxf(mm, red[i]);
    __syncthreads();

    float z = 0.f;
    for (int j = t; j <= Ln; j += 256) z += expf(sc[j] - mm);
#pragma unroll
    for (int off = 16; off; off >>= 1) z += __shfl_xor_sync(0xffffffffu, z, off);
    if ((t & 31) == 0) red[t >> 5] = z;
    __syncthreads();
    if (t == 0) {
        float tot = 0.f;
#pragma unroll
        for (int i = 0; i < 8; i++) tot += red[i];
        g_pm[bh] = mm;
        g_ps[bh] = tot;
    }
}

// ---------------------------------------------------------------------------
// rel weighted row-sum: grid (Bn, NSP=32); 128 keys per chunk.
// upart[(b*NSP+sp)*8+h][:] = sum_{j in chunk} p_hj * cur_b[j]
// ---------------------------------------------------------------------------
__global__ __launch_bounds__(256)
void rel_wsum_kernel() {
    __shared__ float p[8][128];
    __shared__ float mz[16];
    int b = blockIdx.x, sp = blockIdx.y;
    int t = threadIdx.x;
    if (t < 8)       mz[t] = g_pm[b * 8 + t];
    else if (t < 16) mz[t] = 1.f / g_ps[b * 8 + (t - 8)];
    __syncthreads();
    for (int i = t; i < 8 * 128; i += 256) {
        int hh = i >> 7, jj = i & 127;
        p[hh][jj] = expf(g_sc[(b * 8 + hh) * SCW + 1 + sp * 128 + jj] - mz[hh])
                    * mz[8 + hh];
    }
    __syncthreads();

    int h = t >> 5, kg = t & 31;
    float a0x = 0.f, a0y = 0.f, a0z = 0.f, a0w = 0.f;
    float a1x = 0.f, a1y = 0.f, a1z = 0.f, a1w = 0.f;
    for (int jj = 0; jj < 128; jj++) {
        size_t row = (size_t)(b * Ln + sp * 128 + jj) * Hn + kg * 8;
        float4 c0 = *(const float4*)(g_cur + row);
        float4 c1 = *(const float4*)(g_cur + row + 4);
        float pp = p[h][jj];
        a0x += pp * c0.x; a0y += pp * c0.y; a0z += pp * c0.z; a0w += pp * c0.w;
        a1x += pp * c1.x; a1y += pp * c1.y; a1z += pp * c1.z; a1w += pp * c1.w;
    }
    size_t o = (size_t)((b * NSP + sp) * 8 + h) * Hn + kg * 8;
    *(float4*)(g_upart + o)     = make_float4(a0x, a0y, a0z, a0w);
    *(float4*)(g_upart + o + 4) = make_float4(a1x, a1y, a1z, a1w);
}

// ---------------------------------------------------------------------------
// rel epilogue: u = sum_sp upart + p0*center; cx = u@Wrv + bv;
// dst = LN(relu(cx@Wo + bo + center)); also updates g_center
// ---------------------------------------------------------------------------
__global__ __launch_bounds__(256)
void rel_epi_kernel(const float* __restrict__ Wrv, const float* __restrict__ brv,
                    const float* __restrict__ Wo, const float* __restrict__ bo,
                    const float* __restrict__ lnw, const float* __restrict__ lnb,
                    float* __restrict__ dst) {
    __shared__ float u[8][Hn];
    __shared__ float cx[Hn];
    __shared__ float red[8];
    int b = blockIdx.x;
    int n = threadIdx.x;

    float ctr = g_center[b * Hn + n];
#pragma unroll
    for (int h = 0; h < 8; h++) {
        float s = 0.f;
        for (int sp = 0; sp < NSP; sp++)
            s += g_upart[(size_t)((b * NSP + sp) * 8 + h) * Hn + n];
        float p0 = expf(g_sc[(b * 8 + h) * SCW] - g_pm[b * 8 + h]) / g_ps[b * 8 + h];
        u[h][n] = s + p0 * ctr;
    }
    __syncthreads();

    int h = n >> 5;
    float cval = 0.f;
#pragma unroll 8
    for (int k = 0; k < Hn; k++) cval += u[h][k] * Wrv[(size_t)k * Hn + n];
    cx[n] = cval + brv[n];
    __syncthreads();

    float s = 0.f;
#pragma unroll 8
    for (int k = 0; k < Hn; k++) s += cx[k] * Wo[(size_t)k * Hn + n];
    float v = fmaxf(s + bo[n] + ctr, 0.f);

    float r = v;
#pragma unroll
    for (int off = 16; off; off >>= 1) r += __shfl_xor_sync(0xffffffffu, r, off);
    if ((n & 31) == 0) red[n >> 5] = r;
    __syncthreads();
    float tot = 0.f;
#pragma unroll
    for (int i = 0; i < 8; i++) tot += red[i];
    float mean = tot * (1.f / Hn);
    __syncthreads();

    float dv = v - mean;
    float r2 = dv * dv;
#pragma unroll
    for (int off = 16; off; off >>= 1) r2 += __shfl_xor_sync(0xffffffffu, r2, off);
    if ((n & 31) == 0) red[n >> 5] = r2;
    __syncthreads();
    tot = 0.f;
#pragma unroll
    for (int i = 0; i < 8; i++) tot += red[i];
    float var = tot * (1.f / Hn);

    float o = lnw[n] * dv * rsqrtf(var + LNEPS) + lnb[n];
    g_center[b * Hn + n] = o;
    dst[b * Hn + n] = o;
}

// ---------------------------------------------------------------------------
extern "C" void kernel_launch(void* const* d_in, const int* in_sizes, int n_in,
                              void* d_out, int out_size) {
    const float* x     = (const float*)d_in[0];
    const float* satWq = (const float*)d_in[1];  const float* satbq = (const float*)d_in[2];
    const float* satWk = (const float*)d_in[3];  const float* satbk = (const float*)d_in[4];
    const float* satWv = (const float*)d_in[5];  const float* satbv = (const float*)d_in[6];
    const float* satWo = (const float*)d_in[7];  const float* satbo = (const float*)d_in[8];
    const float* relWq = (const float*)d_in[9];  const float* relbq = (const float*)d_in[10];
    const float* relWk = (const float*)d_in[11]; const float* relbk = (const float*)d_in[12];
    const float* relWv = (const float*)d_in[13]; const float* relbv = (const float*)d_in[14];
    const float* relWo = (const float*)d_in[15]; const float* relbo = (const float*)d_in[16];
    const float* slnw  = (const float*)d_in[17]; const float* slnb  = (const float*)d_in[18];
    const float* rlnw  = (const float*)d_in[19]; const float* rlnb  = (const float*)d_in[20];
    float* out = (float*)d_out;
    (void)relbk;   // key bias cancels in softmax

    float *cur, *Q, *Kc, *Vc, *Kx, *Vx, *tmp, *center;
    __half *curP, *ctxP, *BT;
    cudaGetSymbolAddress((void**)&cur,  g_cur);
    cudaGetSymbolAddress((void**)&Q,    g_Q);
    cudaGetSymbolAddress((void**)&Kc,   g_Kc);
    cudaGetSymbolAddress((void**)&Vc,   g_Vc);
    cudaGetSymbolAddress((void**)&Kx,   g_Kx);
    cudaGetSymbolAddress((void**)&Vx,   g_Vx);
    cudaGetSymbolAddress((void**)&tmp,  g_tmp);
    cudaGetSymbolAddress((void**)&curP, g_curP);
    cudaGetSymbolAddress((void**)&ctxP, g_ctxP);
    cudaGetSymbolAddress((void**)&BT,   g_BT);
    cudaGetSymbolAddress((void**)&center, g_center);

    cudaFuncSetAttribute(hgemm2, cudaFuncAttributeMaxDynamicSharedMemorySize,
                         GEMM_SMEM);

    // fp16 weights: 0 satWq, 1 satWk, 2 satWv, 3 satWo
    wprep_kernel<<<dim3(Hn, 4), Hn>>>(satWq, satWk, satWv, satWo);

    splitcopy_kernel<<<Mn * Hn / 8 / 256, 256>>>(x);
    meanpart_kernel<<<dim3(16, Bn), Hn>>>(x);

    const __half* Wq = BT + (size_t)0 * Hn * Hn;
    const __half* Wk = BT + (size_t)1 * Hn * Hn;
    const __half* Wv = BT + (size_t)2 * Hn * Hn;
    const __half* Wo = BT + (size_t)3 * Hn * Hn;

    for (int it = 0; it < 2; it++) {
        proj_center_kernel<<<dim3(3 * Bn, 8), Hn>>>(
            satWk, satbk, satWv, satbv, relWq, relbq, it == 0 ? 1 : 0);
        rel_wtil_kernel<<<Bn * NHn, Hn>>>(relWk);   // before GEMMs: ln_rows needs w~
        // iter 0: cur == x, so K/V projections double as loop-invariant Kx/Vx
        float* Kdst = (it == 0) ? Kx : Kc;
        float* Vdst = (it == 0) ? Vx : Vc;
        hgemm2<<<dim3(Mn / 128, 3), 256, GEMM_SMEM>>>(
            curP, Wq, Wk, Wv, satbq, satbk, satbv, Q, Kdst, Vdst);
        sat_attn_kernel<<<Mn, 256>>>(Kdst, Vdst);
        hgemm2<<<dim3(Mn / 128, 1), 256, GEMM_SMEM>>>(
            ctxP, Wo, Wo, Wo, satbo, satbo, satbo, tmp, tmp, tmp);
        float* dup = (it == 0) ? (float*)nullptr : out;
        ln_rows_kernel<<<Mn / 8, 256>>>(tmp, cur, dup, slnw, slnb);

        rel_stat_kernel<<<Bn * NHn, 256>>>();
        rel_wsum_kernel<<<dim3(Bn, NSP), 256>>>();
        float* cdst = (it == 0) ? center : (out + (size_t)Mn * Hn);
        rel_epi_kernel<<<Bn, Hn>>>(relWv, relbv, relWo, relbo, rlnw, rlnb, cdst);
    }
}

// round 15
// speedup vs baseline: 1.4600x; 1.0281x over previous
#include <cuda_runtime.h>
#include <cuda_fp16.h>
#include <math.h>
#include <stdint.h>

// ---------------------------------------------------------------------------
// StarTransformerLayer, GB300 (compute_103 -> mma.sync path).
// B=8, L=4096, H=256, NH=8, HD=32, 2 iterations.
// R14 = R12 retried on a clean node. R12's +41% regression is attributed to
// DVFS throttle (sentinel: proj_center 7.6us vs 6.4us clean for identical
// code). fp16 attention operands (Q/Kc/Vc/Kx/Vx) halve sat_attn + QKV-store
// traffic; Wo output stays fp32 (LN residual). rel_err measured 5.72e-4.
// ---------------------------------------------------------------------------

namespace {
constexpr int Bn  = 8;
constexpr int Ln  = 4096;
constexpr int Hn  = 256;
constexpr int NHn = 8;
constexpr int HDn = 32;
constexpr int Mn  = Bn * Ln;          // 32768
constexpr int KA  = 256;              // fp16 A columns
constexpr int SCW = 4128;             // score row stride (4097 used)
constexpr int NSP = 32;               // wsum chunks (128 keys each)
constexpr float SCALE = 0.17677669529663688f;   // 1/sqrt(32)
constexpr float LNEPS = 1e-12f;
// GEMM tiling
constexpr int KC   = 32;
constexpr int NC   = KA / KC;         // 8 chunks
constexpr int LDA  = 40;              // 32 + 8 pad (halfs)
constexpr int LDB  = 264;             // 256 + 8 pad (halfs)
constexpr int ASZ  = 128 * LDA;       // 5120 halfs
constexpr int BSZ  = KC * LDB;        // 8448 halfs
constexpr int STG  = ASZ + BSZ;       // 13568 halfs
constexpr int GEMM_SMEM = STG * 2 * 4;   // 108544 bytes (4 stages)
}

// ---- scratch (device globals) ---------------------------------------------
__device__ float  g_cur [Mn * Hn];
__device__ __align__(16) __half g_curP[(size_t)Mn * KA];
__device__ __align__(16) __half g_ctxP[(size_t)Mn * KA];
__device__ __align__(16) __half g_BT  [4 * (size_t)Hn * Hn];
// fp16 attention operands (sat_attn consumers only)
__device__ __align__(16) __half g_Qh [(size_t)Mn * Hn];
__device__ __align__(16) __half g_Kch[(size_t)Mn * Hn];
__device__ __align__(16) __half g_Vch[(size_t)Mn * Hn];
__device__ __align__(16) __half g_Kxh[(size_t)Mn * Hn];
__device__ __align__(16) __half g_Vxh[(size_t)Mn * Hn];
__device__ float  g_tmp [Mn * Hn];

__device__ float g_center[Bn * Hn];
// center projections, 8 k-partials: [ks][sel][b*Hn+n]; sel 0=Kcen 1=Vcen 2=Qrel
__device__ float g_cproj[8][3][Bn * Hn];
__device__ float g_cpart[Bn * 16 * Hn];

// rel attention scratch
__device__ float g_wtil[64 * Hn];            // per (b,h): w~ (includes SCALE)
__device__ float g_sc  [64 * SCW];           // scores, jidx 0..4096
__device__ float g_pm  [64];                 // per-bh max
__device__ float g_ps  [64];                 // per-bh sum-exp
__device__ float g_upart[(size_t)Bn * NSP * NHn * Hn];   // partial wsums

// ---------------------------------------------------------------------------
// helpers
// ---------------------------------------------------------------------------
__device__ __forceinline__ uint32_t smem_u32(const void* p) {
    uint32_t a;
    asm("{ .reg .u64 t; cvta.to.shared.u64 t, %1; cvt.u32.u64 %0, t; }"
        : "=r"(a) : "l"(p));
    return a;
}
__device__ __forceinline__ void cp16(uint32_t s, const void* g) {
    asm volatile("cp.async.cg.shared.global [%0], [%1], 16;" :: "r"(s), "l"(g));
}
__device__ __forceinline__ void cp_commit() {
    asm volatile("cp.async.commit_group;" ::: "memory");
}
__device__ __forceinline__ void ldm_x4(uint32_t* r, uint32_t a) {
    asm volatile("ldmatrix.sync.aligned.m8n8.x4.shared.b16 {%0,%1,%2,%3}, [%4];"
                 : "=r"(r[0]), "=r"(r[1]), "=r"(r[2]), "=r"(r[3]) : "r"(a));
}
__device__ __forceinline__ void ldm_x4t(uint32_t* r, uint32_t a) {
    asm volatile("ldmatrix.sync.aligned.m8n8.x4.trans.shared.b16 {%0,%1,%2,%3}, [%4];"
                 : "=r"(r[0]), "=r"(r[1]), "=r"(r[2]), "=r"(r[3]) : "r"(a));
}
__device__ __forceinline__ void mma16816(float* c, const uint32_t* a,
                                         const uint32_t* b) {
    asm volatile(
        "mma.sync.aligned.m16n8k16.row.col.f32.f16.f16.f32 "
        "{%0,%1,%2,%3}, {%4,%5,%6,%7}, {%8,%9}, {%0,%1,%2,%3};"
        : "+f"(c[0]), "+f"(c[1]), "+f"(c[2]), "+f"(c[3])
        : "r"(a[0]), "r"(a[1]), "r"(a[2]), "r"(a[3]), "r"(b[0]), "r"(b[1]));
}

// ---------------------------------------------------------------------------
// GEMM: C[M,256] = A[M,256](fp16) @ B[256,256](fp16) + bias.  CTA 128x256,
// 8 warps 64x64, KC=32, 4-stage cp.async. blockIdx.y selects weight set.
// HOUT: store __half (attention operands) vs float (LN residual input).
// ---------------------------------------------------------------------------
template <bool HOUT>
__global__ __launch_bounds__(256, 1)
void hgemm2(const __half* __restrict__ Ap,
            const __half* B0, const __half* B1, const __half* B2,
            const float* bias0, const float* bias1, const float* bias2,
            void* C0, void* C1, void* C2) {
    extern __shared__ __align__(16) __half smh[];
    const int tid = threadIdx.x;
    const int bm = blockIdx.x * 128;
    const int wsel = blockIdx.y;
    const __half* Bp  = (wsel == 0) ? B0 : (wsel == 1) ? B1 : B2;
    const float*  bias = (wsel == 0) ? bias0 : (wsel == 1) ? bias1 : bias2;
    void*         C   = (wsel == 0) ? C0 : (wsel == 1) ? C1 : C2;
    const uint32_t sbase = smem_u32(smh);

    auto load_chunk = [&](int j, int s) {
        const uint32_t st = sbase + (uint32_t)(s * STG) * 2;
#pragma unroll
        for (int i = 0; i < 2; i++) {          // A: 512 16B segs
            int seg = tid + i * 256;
            int r = seg >> 2, c = seg & 3;
            cp16(st + (uint32_t)(r * LDA + c * 8) * 2,
                 Ap + (size_t)(bm + r) * KA + j * KC + c * 8);
        }
#pragma unroll
        for (int i = 0; i < 4; i++) {          // B: 1024 16B segs
            int seg = tid + i * 256;
            int r = seg >> 5, c = seg & 31;
            cp16(st + (uint32_t)(ASZ + r * LDB + c * 8) * 2,
                 Bp + (size_t)(j * KC + r) * Hn + c * 8);
        }
        cp_commit();
    };

    const int warp = tid >> 5, lane = tid & 31;
    const int wm = (warp & 1) * 64;
    const int wn = (warp >> 1) * 64;
    const int lr = lane & 15;
    const int lg8 = (lane >> 4) * 8;

    float acc[4][8][4];
#pragma unroll
    for (int mi = 0; mi < 4; mi++)
#pragma unroll
        for (int ni = 0; ni < 8; ni++)
#pragma unroll
            for (int k = 0; k < 4; k++) acc[mi][ni][k] = 0.f;

    load_chunk(0, 0);
    load_chunk(1, 1);
    load_chunk(2, 2);

    for (int j = 0; j < NC; j++) {
        asm volatile("cp.async.wait_group 2;" ::: "memory");
        __syncthreads();
        if (j + 3 < NC) load_chunk(j + 3, (j + 3) & 3);
        else            cp_commit();           // constant group depth

        const uint32_t st = sbase + (uint32_t)((j & 3) * STG) * 2;
#pragma unroll
        for (int ks = 0; ks < KC; ks += 16) {
            uint32_t a[4][4];
#pragma unroll
            for (int mi = 0; mi < 4; mi++)
                ldm_x4(a[mi], st + (uint32_t)((wm + mi * 16 + lr) * LDA + ks + lg8) * 2);
            uint32_t b[4][4];
#pragma unroll
            for (int np = 0; np < 4; np++)
                ldm_x4t(b[np], st + (uint32_t)(ASZ + (ks + lr) * LDB
                                               + wn + np * 16 + lg8) * 2);
#pragma unroll
            for (int mi = 0; mi < 4; mi++)
#pragma unroll
                for (int ni = 0; ni < 8; ni++)
                    mma16816(acc[mi][ni], a[mi], &b[ni >> 1][(ni & 1) * 2]);
        }
    }

    const int g = lane >> 2, tg = (lane & 3) * 2;
#pragma unroll
    for (int mi = 0; mi < 4; mi++) {
#pragma unroll
        for (int ni = 0; ni < 8; ni++) {
            int row = bm + wm + mi * 16 + g;
            int col = wn + ni * 8 + tg;
            float b0 = bias[col], b1 = bias[col + 1];
            float v00 = acc[mi][ni][0] + b0, v01 = acc[mi][ni][1] + b1;
            float v10 = acc[mi][ni][2] + b0, v11 = acc[mi][ni][3] + b1;
            if (HOUT) {
                __half* Ch = (__half*)C;
                *(__half2*)(Ch + (size_t)row * Hn + col) =
                    __floats2half2_rn(v00, v01);
                *(__half2*)(Ch + (size_t)(row + 8) * Hn + col) =
                    __floats2half2_rn(v10, v11);
            } else {
                float* Cf = (float*)C;
                *(float2*)(Cf + (size_t)row * Hn + col) = make_float2(v00, v01);
                *(float2*)(Cf + (size_t)(row + 8) * Hn + col) = make_float2(v10, v11);
            }
        }
    }
}

// ---------------------------------------------------------------------------
// weight prep: fp16(W) for the 4 sat weights
// ---------------------------------------------------------------------------
__global__ void wprep_kernel(const float* W0, const float* W1, const float* W2,
                             const float* W3) {
    const float* Ws[4] = {W0, W1, W2, W3};
    int wi = blockIdx.y;
    int k = blockIdx.x, n = threadIdx.x;
    g_BT[(size_t)wi * Hn * Hn + (size_t)k * Hn + n] =
        __float2half_rn(Ws[wi][(size_t)k * Hn + n]);
}

// x -> cur (fp32) + curP (fp16)
__global__ void splitcopy_kernel(const float* __restrict__ x) {
    int t = blockIdx.x * blockDim.x + threadIdx.x;   // Mn*Hn/8
    int row = t >> 5;
    int k0 = (t & 31) * 8;
    const float4* src = (const float4*)(x + (size_t)row * Hn + k0);
    float4* dst = (float4*)(g_cur + (size_t)row * Hn + k0);
    float4 v0 = src[0], v1 = src[1];
    dst[0] = v0; dst[1] = v1;
    __half hi[8];
    float vv[8] = {v0.x, v0.y, v0.z, v0.w, v1.x, v1.y, v1.z, v1.w};
#pragma unroll
    for (int j = 0; j < 8; j++) hi[j] = __float2half_rn(vv[j]);
    *(uint4*)(g_curP + (size_t)row * KA + k0) = *(uint4*)hi;
}

// partial column sums of x over L (stage 1 of mean)
__global__ void meanpart_kernel(const float* __restrict__ x) {
    int c = blockIdx.x, b = blockIdx.y, h = threadIdx.x;
    const float* p = x + ((size_t)b * Ln + c * 256) * Hn + h;
    float s = 0.f;
    for (int l = 0; l < 256; l++) s += p[(size_t)l * Hn];
    g_cpart[(b * 16 + c) * Hn + h] = s;
}

// ---------------------------------------------------------------------------
// center projections, 8-way k-split: grid (3*Bn, 8).
// ---------------------------------------------------------------------------
__global__ void proj_center_kernel(
    const float* __restrict__ satWk, const float* __restrict__ satbk,
    const float* __restrict__ satWv, const float* __restrict__ satbv,
    const float* __restrict__ relWq, const float* __restrict__ relbq,
    int use_cpart) {
    __shared__ float c[32];
    int b   = blockIdx.x % Bn;
    int sel = blockIdx.x / Bn;
    int ks  = blockIdx.y;
    int n   = threadIdx.x;
    int k0  = ks * 32;
    if (n < 32) {
        int k = k0 + n;
        float v;
        if (use_cpart) {
            float s = 0.f;
#pragma unroll
            for (int i = 0; i < 16; i++) s += g_cpart[(b * 16 + i) * Hn + k];
            v = s * (1.f / Ln);
            if (sel == 0) g_center[b * Hn + k] = v;
        } else {
            v = g_center[b * Hn + k];
        }
        c[n] = v;
    }
    __syncthreads();
    const float* W; const float* bi;
    switch (sel) {
        case 0: W = satWk; bi = satbk; break;
        case 1: W = satWv; bi = satbv; break;
        default: W = relWq; bi = relbq; break;
    }
    float s = 0.f;
#pragma unroll
    for (int k = 0; k < 32; k++) s += c[k] * W[(size_t)(k0 + k) * Hn + n];
    if (ks == 0) s += bi[n];
    g_cproj[ks][sel][b * Hn + n] = s;
}

// ---------------------------------------------------------------------------
// rel: w~_bh[k] = SCALE * sum_d Wrk[k][h*32+d] * qrel_bh[d]; s0 = center.w~
// ---------------------------------------------------------------------------
__global__ __launch_bounds__(256)
void rel_wtil_kernel(const float* __restrict__ relWk) {
    __shared__ float q[HDn];
    __shared__ float red[8];
    int bh = blockIdx.x;
    int b = bh >> 3, h = bh & 7;
    int t = threadIdx.x;
    if (t < HDn) {
        int i = b * Hn + h * HDn + t;
        float s = 0.f;
#pragma unroll
        for (int pp = 0; pp < 8; pp++) s += g_cproj[pp][2][i];
        q[t] = s;
    }
    __syncthreads();
    float w = 0.f;
#pragma unroll 8
    for (int d = 0; d < HDn; d++)
        w += relWk[(size_t)t * Hn + h * HDn + d] * q[d];
    w *= SCALE;
    g_wtil[bh * Hn + t] = w;

    // s0 = center . w~
    float c = g_center[b * Hn + t] * w;
#pragma unroll
    for (int off = 16; off; off >>= 1) c += __shfl_xor_sync(0xffffffffu, c, off);
    if ((t & 31) == 0) red[t >> 5] = c;
    __syncthreads();
    if (t == 0) {
        float tot = 0.f;
#pragma unroll
        for (int i = 0; i < 8; i++) tot += red[i];
        g_sc[bh * SCW] = tot;
    }
}

// ---------------------------------------------------------------------------
// satellite attention (fp16 operands) -> writes ctxP (fp16)
// ---------------------------------------------------------------------------
__global__ __launch_bounds__(256)
void sat_attn_kernel(const __half* __restrict__ Kc, const __half* __restrict__ Vc) {
    int token = blockIdx.x;
    int b = token >> 12;
    int l = token & (Ln - 1);
    int h = threadIdx.x >> 5;
    int d = threadIdx.x & 31;
    int col = h * HDn + d;

    size_t ic   = (size_t)token * Hn + col;
    int lb = (l + 1) & (Ln - 1);
    int la = (l == 0) ? (Ln - 1) : 0;
    size_t ibe  = ((size_t)(b * Ln + lb)) * Hn + col;
    size_t iaf  = ((size_t)(b * Ln + la)) * Hn + col;
    int icen = b * Hn + col;

    float kcen = 0.f, vcen = 0.f;
#pragma unroll
    for (int pp = 0; pp < 8; pp++) {
        kcen += g_cproj[pp][0][icen];
        vcen += g_cproj[pp][1][icen];
    }

    float q  = __half2float(g_Qh[ic]);
    float s0 = q * __half2float(Kc[ibe]);
    float s1 = q * __half2float(Kc[ic]);
    float s2 = q * __half2float(Kc[iaf]);
    float s3 = q * __half2float(g_Kxh[ic]);
    float s4 = q * kcen;
#pragma unroll
    for (int off = 16; off; off >>= 1) {
        s0 += __shfl_xor_sync(0xffffffffu, s0, off);
        s1 += __shfl_xor_sync(0xffffffffu, s1, off);
        s2 += __shfl_xor_sync(0xffffffffu, s2, off);
        s3 += __shfl_xor_sync(0xffffffffu, s3, off);
        s4 += __shfl_xor_sync(0xffffffffu, s4, off);
    }
    s0 *= SCALE; s1 *= SCALE; s2 *= SCALE; s3 *= SCALE; s4 *= SCALE;
    float mx = fmaxf(fmaxf(fmaxf(s0, s1), fmaxf(s2, s3)), s4);
    float e0 = expf(s0 - mx), e1 = expf(s1 - mx), e2 = expf(s2 - mx);
    float e3 = expf(s3 - mx), e4 = expf(s4 - mx);
    float inv = 1.f / (e0 + e1 + e2 + e3 + e4);
    float ctx = (e0 * __half2float(Vc[ibe]) + e1 * __half2float(Vc[ic]) +
                 e2 * __half2float(Vc[iaf]) + e3 * __half2float(g_Vxh[ic]) +
                 e4 * vcen) * inv;

    g_ctxP[(size_t)token * KA + col] = __float2half_rn(ctx);
}

// ---------------------------------------------------------------------------
// LN(relu(tmp + cur)) -> cur + curP + REL SCORES (8 heads per row).
// ---------------------------------------------------------------------------
__global__ __launch_bounds__(256)
void ln_rows_kernel(const float* __restrict__ tmp, float* __restrict__ cur,
                    float* __restrict__ dup,
                    const float* __restrict__ w, const float* __restrict__ bvec) {
    __shared__ float wts[8][Hn];     // 8 KB: w~ for this block's batch
    int warp = threadIdx.x >> 5;
    int lane = threadIdx.x & 31;
    int row = blockIdx.x * 8 + warp;
    int b = row >> 12;
    int l = row & (Ln - 1);
    int k0 = lane * 8;
    size_t base = (size_t)row * Hn + k0;

    for (int i = threadIdx.x; i < 8 * Hn; i += 256)
        wts[i >> 8][i & 255] = g_wtil[(b * 8 + (i >> 8)) * Hn + (i & 255)];
    __syncthreads();

    float4 t0 = *(const float4*)(tmp + base);
    float4 t1 = *(const float4*)(tmp + base + 4);
    float4 c0 = *(const float4*)(cur + base);
    float4 c1 = *(const float4*)(cur + base + 4);
    float v[8] = { fmaxf(t0.x + c0.x, 0.f), fmaxf(t0.y + c0.y, 0.f),
                   fmaxf(t0.z + c0.z, 0.f), fmaxf(t0.w + c0.w, 0.f),
                   fmaxf(t1.x + c1.x, 0.f), fmaxf(t1.y + c1.y, 0.f),
                   fmaxf(t1.z + c1.z, 0.f), fmaxf(t1.w + c1.w, 0.f) };

    float s = 0.f;
#pragma unroll
    for (int j = 0; j < 8; j++) s += v[j];
#pragma unroll
    for (int off = 16; off; off >>= 1) s += __shfl_xor_sync(0xffffffffu, s, off);
    float mean = s * (1.f / Hn);

    float s2 = 0.f;
#pragma unroll
    for (int j = 0; j < 8; j++) { float d = v[j] - mean; s2 += d * d; }
#pragma unroll
    for (int off = 16; off; off >>= 1) s2 += __shfl_xor_sync(0xffffffffu, s2, off);
    float rstd = rsqrtf(s2 * (1.f / Hn) + LNEPS);

    float4 w0 = *(const float4*)(w + k0);
    float4 w1 = *(const float4*)(w + k0 + 4);
    float4 b0 = *(const float4*)(bvec + k0);
    float4 b1 = *(const float4*)(bvec + k0 + 4);
    float ww[8] = {w0.x, w0.y, w0.z, w0.w, w1.x, w1.y, w1.z, w1.w};
    float bb[8] = {b0.x, b0.y, b0.z, b0.w, b1.x, b1.y, b1.z, b1.w};

    float o[8];
    __half hi[8];
#pragma unroll
    for (int j = 0; j < 8; j++) {
        o[j] = ww[j] * (v[j] - mean) * rstd + bb[j];
        hi[j] = __float2half_rn(o[j]);
    }
    float4 oo0 = make_float4(o[0], o[1], o[2], o[3]);
    float4 oo1 = make_float4(o[4], o[5], o[6], o[7]);
    *(float4*)(cur + base)     = oo0;
    *(float4*)(cur + base + 4) = oo1;
    if (dup) {
        *(float4*)(dup + base)     = oo0;
        *(float4*)(dup + base + 4) = oo1;
    }
    *(uint4*)(g_curP + (size_t)row * KA + k0) = *(uint4*)hi;

    // rel scores: s_h = row . w~_h  (new cur row still in registers)
#pragma unroll
    for (int h = 0; h < 8; h++) {
        float p = 0.f;
#pragma unroll
        for (int j = 0; j < 8; j++) p += o[j] * wts[h][k0 + j];
#pragma unroll
        for (int off = 16; off; off >>= 1)
            p += __shfl_xor_sync(0xffffffffu, p, off);
        if (lane == 0)
            g_sc[(b * 8 + h) * SCW + 1 + l] = p;
    }
}

// ---------------------------------------------------------------------------
// rel softmax stats: per bh, max + sum-exp over 4097 scores
// ---------------------------------------------------------------------------
__global__ __launch_bounds__(256)
void rel_stat_kernel() {
    __shared__ float red[8];
    int bh = blockIdx.x;
    int t = threadIdx.x;
    const float* sc = g_sc + bh * SCW;

    float m = -1e30f;
    for (int j = t; j <= Ln; j += 256) m = fmaxf(m, sc[j]);
#pragma unroll
    for (int off = 16; off; off >>= 1)
        m = fmaxf(m, __shfl_xor_sync(0xffffffffu, m, off));
    if ((t & 31) == 0) red[t >> 5] = m;
    __syncthreads();
    float mm = -1e30f;
#pragma unroll
    for (int i = 0; i < 8; i++) mm = fmaxf(mm, red[i]);
    __syncthreads();

    float z = 0.f;
    for (int j = t; j <= Ln; j += 256) z += expf(sc[j] - mm);
#pragma unroll
    for (int off = 16; off; off >>= 1) z += __shfl_xor_sync(0xffffffffu, z, off);
    if ((t & 31) == 0) red[t >> 5] = z;
    __syncthreads();
    if (t == 0) {
        float tot = 0.f;
#pragma unroll
        for (int i = 0; i < 8; i++) tot += red[i];
        g_pm[bh] = mm;
        g_ps[bh] = tot;
    }
}

// ---------------------------------------------------------------------------
// rel weighted row-sum: grid (Bn, NSP=32); 128 keys per chunk.
// ---------------------------------------------------------------------------
__global__ __launch_bounds__(256)
void rel_wsum_kernel() {
    __shared__ float p[8][128];
    __shared__ float mz[16];
    int b = blockIdx.x, sp = blockIdx.y;
    int t = threadIdx.x;
    if (t < 8)       mz[t] = g_pm[b * 8 + t];
    else if (t < 16) mz[t] = 1.f / g_ps[b * 8 + (t - 8)];
    __syncthreads();
    for (int i = t; i < 8 * 128; i += 256) {
        int hh = i >> 7, jj = i & 127;
        p[hh][jj] = expf(g_sc[(b * 8 + hh) * SCW + 1 + sp * 128 + jj] - mz[hh])
                    * mz[8 + hh];
    }
    __syncthreads();

    int h = t >> 5, kg = t & 31;
    float a0x = 0.f, a0y = 0.f, a0z = 0.f, a0w = 0.f;
    float a1x = 0.f, a1y = 0.f, a1z = 0.f, a1w = 0.f;
    for (int jj = 0; jj < 128; jj++) {
        size_t row = (size_t)(b * Ln + sp * 128 + jj) * Hn + kg * 8;
        float4 c0 = *(const float4*)(g_cur + row);
        float4 c1 = *(const float4*)(g_cur + row + 4);
        float pp = p[h][jj];
        a0x += pp * c0.x; a0y += pp * c0.y; a0z += pp * c0.z; a0w += pp * c0.w;
        a1x += pp * c1.x; a1y += pp * c1.y; a1z += pp * c1.z; a1w += pp * c1.w;
    }
    size_t o = (size_t)((b * NSP + sp) * 8 + h) * Hn + kg * 8;
    *(float4*)(g_upart + o)     = make_float4(a0x, a0y, a0z, a0w);
    *(float4*)(g_upart + o + 4) = make_float4(a1x, a1y, a1z, a1w);
}

// ---------------------------------------------------------------------------
// rel epilogue: u = sum_sp upart + p0*center; cx = u@Wrv + bv;
// dst = LN(relu(cx@Wo + bo + center)); also updates g_center
// ---------------------------------------------------------------------------
__global__ __launch_bounds__(256)
void rel_epi_kernel(const float* __restrict__ Wrv, const float* __restrict__ brv,
                    const float* __restrict__ Wo, const float* __restrict__ bo,
                    const float* __restrict__ lnw, const float* __restrict__ lnb,
                    float* __restrict__ dst) {
    __shared__ float u[8][Hn];
    __shared__ float cx[Hn];
    __shared__ float red[8];
    int b = blockIdx.x;
    int n = threadIdx.x;

    float ctr = g_center[b * Hn + n];
#pragma unroll
    for (int h = 0; h < 8; h++) {
        float s = 0.f;
        for (int sp = 0; sp < NSP; sp++)
            s += g_upart[(size_t)((b * NSP + sp) * 8 + h) * Hn + n];
        float p0 = expf(g_sc[(b * 8 + h) * SCW] - g_pm[b * 8 + h]) / g_ps[b * 8 + h];
        u[h][n] = s + p0 * ctr;
    }
    __syncthreads();

    int h = n >> 5;
    float cval = 0.f;
#pragma unroll 8
    for (int k = 0; k < Hn; k++) cval += u[h][k] * Wrv[(size_t)k * Hn + n];
    cx[n] = cval + brv[n];
    __syncthreads();

    float s = 0.f;
#pragma unroll 8
    for (int k = 0; k < Hn; k++) s += cx[k] * Wo[(size_t)k * Hn + n];
    float v = fmaxf(s + bo[n] + ctr, 0.f);

    float r = v;
#pragma unroll
    for (int off = 16; off; off >>= 1) r += __shfl_xor_sync(0xffffffffu, r, off);
    if ((n & 31) == 0) red[n >> 5] = r;
    __syncthreads();
    float tot = 0.f;
#pragma unroll
    for (int i = 0; i < 8; i++) tot += red[i];
    float mean = tot * (1.f / Hn);
    __syncthreads();

    float dv = v - mean;
    float r2 = dv * dv;
#pragma unroll
    for (int off = 16; off; off >>= 1) r2 += __shfl_xor_sync(0xffffffffu, r2, off);
    if ((n & 31) == 0) red[n >> 5] = r2;
    __syncthreads();
    tot = 0.f;
#pragma unroll
    for (int i = 0; i < 8; i++) tot += red[i];
    float var = tot * (1.f / Hn);

    float o = lnw[n] * dv * rsqrtf(var + LNEPS) + lnb[n];
    g_center[b * Hn + n] = o;
    dst[b * Hn + n] = o;
}

// ---------------------------------------------------------------------------
extern "C" void kernel_launch(void* const* d_in, const int* in_sizes, int n_in,
                              void* d_out, int out_size) {
    const float* x     = (const float*)d_in[0];
    const float* satWq = (const float*)d_in[1];  const float* satbq = (const float*)d_in[2];
    const float* satWk = (const float*)d_in[3];  const float* satbk = (const float*)d_in[4];
    const float* satWv = (const float*)d_in[5];  const float* satbv = (const float*)d_in[6];
    const float* satWo = (const float*)d_in[7];  const float* satbo = (const float*)d_in[8];
    const float* relWq = (const float*)d_in[9];  const float* relbq = (const float*)d_in[10];
    const float* relWk = (const float*)d_in[11]; const float* relbk = (const float*)d_in[12];
    const float* relWv = (const float*)d_in[13]; const float* relbv = (const float*)d_in[14];
    const float* relWo = (const float*)d_in[15]; const float* relbo = (const float*)d_in[16];
    const float* slnw  = (const float*)d_in[17]; const float* slnb  = (const float*)d_in[18];
    const float* rlnw  = (const float*)d_in[19]; const float* rlnb  = (const float*)d_in[20];
    float* out = (float*)d_out;
    (void)relbk;   // key bias cancels in softmax

    float *cur, *tmp, *center;
    __half *curP, *ctxP, *BT, *Qh, *Kch, *Vch, *Kxh, *Vxh;
    cudaGetSymbolAddress((void**)&cur,  g_cur);
    cudaGetSymbolAddress((void**)&tmp,  g_tmp);
    cudaGetSymbolAddress((void**)&curP, g_curP);
    cudaGetSymbolAddress((void**)&ctxP, g_ctxP);
    cudaGetSymbolAddress((void**)&BT,   g_BT);
    cudaGetSymbolAddress((void**)&center, g_center);
    cudaGetSymbolAddress((void**)&Qh,  g_Qh);
    cudaGetSymbolAddress((void**)&Kch, g_Kch);
    cudaGetSymbolAddress((void**)&Vch, g_Vch);
    cudaGetSymbolAddress((void**)&Kxh, g_Kxh);
    cudaGetSymbolAddress((void**)&Vxh, g_Vxh);

    cudaFuncSetAttribute(hgemm2<true>, cudaFuncAttributeMaxDynamicSharedMemorySize,
                         GEMM_SMEM);
    cudaFuncSetAttribute(hgemm2<false>, cudaFuncAttributeMaxDynamicSharedMemorySize,
                         GEMM_SMEM);

    // fp16 weights: 0 satWq, 1 satWk, 2 satWv, 3 satWo
    wprep_kernel<<<dim3(Hn, 4), Hn>>>(satWq, satWk, satWv, satWo);

    splitcopy_kernel<<<Mn * Hn / 8 / 256, 256>>>(x);
    meanpart_kernel<<<dim3(16, Bn), Hn>>>(x);

    const __half* Wq = BT + (size_t)0 * Hn * Hn;
    const __half* Wk = BT + (size_t)1 * Hn * Hn;
    const __half* Wv = BT + (size_t)2 * Hn * Hn;
    const __half* Wo = BT + (size_t)3 * Hn * Hn;

    for (int it = 0; it < 2; it++) {
        proj_center_kernel<<<dim3(3 * Bn, 8), Hn>>>(
            satWk, satbk, satWv, satbv, relWq, relbq, it == 0 ? 1 : 0);
        rel_wtil_kernel<<<Bn * NHn, Hn>>>(relWk);   // before GEMMs: ln_rows needs w~
        // iter 0: cur == x, so K/V projections double as loop-invariant Kx/Vx
        __half* Kdst = (it == 0) ? Kxh : Kch;
        __half* Vdst = (it == 0) ? Vxh : Vch;
        hgemm2<true><<<dim3(Mn / 128, 3), 256, GEMM_SMEM>>>(
            curP, Wq, Wk, Wv, satbq, satbk, satbv, Qh, Kdst, Vdst);
        sat_attn_kernel<<<Mn, 256>>>(Kdst, Vdst);
        hgemm2<false><<<dim3(Mn / 128, 1), 256, GEMM_SMEM>>>(
            ctxP, Wo, Wo, Wo, satbo, satbo, satbo, tmp, tmp, tmp);
        float* dup = (it == 0) ? (float*)nullptr : out;
        ln_rows_kernel<<<Mn / 8, 256>>>(tmp, cur, dup, slnw, slnb);

        rel_stat_kernel<<<Bn * NHn, 256>>>();
        rel_wsum_kernel<<<dim3(Bn, NSP), 256>>>();
        float* cdst = (it == 0) ? center : (out + (size_t)Mn * Hn);
        rel_epi_kernel<<<Bn, Hn>>>(relWv, relbv, relWo, relbo, rlnw, rlnb, cdst);
    }
}

// round 16
// speedup vs baseline: 1.4748x; 1.0102x over previous
#include <cuda_runtime.h>
#include <cuda_fp16.h>
#include <math.h>
#include <stdint.h>

// ---------------------------------------------------------------------------
// StarTransformerLayer, GB300 (compute_103 -> mma.sync path).
// B=8, L=4096, H=256, NH=8, HD=32, 2 iterations.
// R16: Wo-GEMM + LayerNorm + rel-score emission fused into one kernel
// (GEMM CTAs own complete rows; LN staged via smem aliasing the dead
// pipeline buffers). g_tmp eliminated. Everything else = R15 (610.8 us).
// fp16 attention operands validated R15 (clean-node sentinel protocol).
// ---------------------------------------------------------------------------

namespace {
constexpr int Bn  = 8;
constexpr int Ln  = 4096;
constexpr int Hn  = 256;
constexpr int NHn = 8;
constexpr int HDn = 32;
constexpr int Mn  = Bn * Ln;          // 32768
constexpr int KA  = 256;              // fp16 A columns
constexpr int SCW = 4128;             // score row stride (4097 used)
constexpr int NSP = 32;               // wsum chunks (128 keys each)
constexpr float SCALE = 0.17677669529663688f;   // 1/sqrt(32)
constexpr float LNEPS = 1e-12f;
// GEMM tiling
constexpr int KC   = 32;
constexpr int NC   = KA / KC;         // 8 chunks
constexpr int LDA  = 40;              // 32 + 8 pad (halfs)
constexpr int LDB  = 264;             // 256 + 8 pad (halfs)
constexpr int ASZ  = 128 * LDA;       // 5120 halfs
constexpr int BSZ  = KC * LDB;        // 8448 halfs
constexpr int STG  = ASZ + BSZ;       // 13568 halfs
constexpr int GEMM_SMEM = STG * 2 * 4;   // 108544 bytes (4 stages)
// fused LN epilogue: sc tile 64 x SCP floats aliases pipeline; wts appended
constexpr int SCP = 264;                 // padded row (floats)
constexpr int LN_SMEM = GEMM_SMEM + 8 * Hn * 4;   // +8KB wts = 116736
}

// ---- scratch (device globals) ---------------------------------------------
__device__ float  g_cur [Mn * Hn];
__device__ __align__(16) __half g_curP[(size_t)Mn * KA];
__device__ __align__(16) __half g_ctxP[(size_t)Mn * KA];
__device__ __align__(16) __half g_BT  [4 * (size_t)Hn * Hn];
// fp16 attention operands (sat_attn consumers only)
__device__ __align__(16) __half g_Qh [(size_t)Mn * Hn];
__device__ __align__(16) __half g_Kch[(size_t)Mn * Hn];
__device__ __align__(16) __half g_Vch[(size_t)Mn * Hn];
__device__ __align__(16) __half g_Kxh[(size_t)Mn * Hn];
__device__ __align__(16) __half g_Vxh[(size_t)Mn * Hn];

__device__ float g_center[Bn * Hn];
// center projections, 8 k-partials: [ks][sel][b*Hn+n]; sel 0=Kcen 1=Vcen 2=Qrel
__device__ float g_cproj[8][3][Bn * Hn];
__device__ float g_cpart[Bn * 16 * Hn];

// rel attention scratch
__device__ float g_wtil[64 * Hn];            // per (b,h): w~ (includes SCALE)
__device__ float g_sc  [64 * SCW];           // scores, jidx 0..4096
__device__ float g_pm  [64];                 // per-bh max
__device__ float g_ps  [64];                 // per-bh sum-exp
__device__ float g_upart[(size_t)Bn * NSP * NHn * Hn];   // partial wsums

// ---------------------------------------------------------------------------
// helpers
// ---------------------------------------------------------------------------
__device__ __forceinline__ uint32_t smem_u32(const void* p) {
    uint32_t a;
    asm("{ .reg .u64 t; cvta.to.shared.u64 t, %1; cvt.u32.u64 %0, t; }"
        : "=r"(a) : "l"(p));
    return a;
}
__device__ __forceinline__ void cp16(uint32_t s, const void* g) {
    asm volatile("cp.async.cg.shared.global [%0], [%1], 16;" :: "r"(s), "l"(g));
}
__device__ __forceinline__ void cp_commit() {
    asm volatile("cp.async.commit_group;" ::: "memory");
}
__device__ __forceinline__ void ldm_x4(uint32_t* r, uint32_t a) {
    asm volatile("ldmatrix.sync.aligned.m8n8.x4.shared.b16 {%0,%1,%2,%3}, [%4];"
                 : "=r"(r[0]), "=r"(r[1]), "=r"(r[2]), "=r"(r[3]) : "r"(a));
}
__device__ __forceinline__ void ldm_x4t(uint32_t* r, uint32_t a) {
    asm volatile("ldmatrix.sync.aligned.m8n8.x4.trans.shared.b16 {%0,%1,%2,%3}, [%4];"
                 : "=r"(r[0]), "=r"(r[1]), "=r"(r[2]), "=r"(r[3]) : "r"(a));
}
__device__ __forceinline__ void mma16816(float* c, const uint32_t* a,
                                         const uint32_t* b) {
    asm volatile(
        "mma.sync.aligned.m16n8k16.row.col.f32.f16.f16.f32 "
        "{%0,%1,%2,%3}, {%4,%5,%6,%7}, {%8,%9}, {%0,%1,%2,%3};"
        : "+f"(c[0]), "+f"(c[1]), "+f"(c[2]), "+f"(c[3])
        : "r"(a[0]), "r"(a[1]), "r"(a[2]), "r"(a[3]), "r"(b[0]), "r"(b[1]));
}

// ---------------------------------------------------------------------------
// QKV GEMM: C[M,256] = A[M,256](fp16) @ B[256,256](fp16) + bias, fp16 out.
// CTA 128x256, 8 warps 64x64, KC=32, 4-stage cp.async. grid.y selects set.
// ---------------------------------------------------------------------------
__global__ __launch_bounds__(256, 1)
void hgemm_qkv(const __half* __restrict__ Ap,
               const __half* B0, const __half* B1, const __half* B2,
               const float* bias0, const float* bias1, const float* bias2,
               __half* C0, __half* C1, __half* C2) {
    extern __shared__ __align__(16) __half smh[];
    const int tid = threadIdx.x;
    const int bm = blockIdx.x * 128;
    const int wsel = blockIdx.y;
    const __half* Bp  = (wsel == 0) ? B0 : (wsel == 1) ? B1 : B2;
    const float*  bias = (wsel == 0) ? bias0 : (wsel == 1) ? bias1 : bias2;
    __half*       C   = (wsel == 0) ? C0 : (wsel == 1) ? C1 : C2;
    const uint32_t sbase = smem_u32(smh);

    auto load_chunk = [&](int j, int s) {
        const uint32_t st = sbase + (uint32_t)(s * STG) * 2;
#pragma unroll
        for (int i = 0; i < 2; i++) {
            int seg = tid + i * 256;
            int r = seg >> 2, c = seg & 3;
            cp16(st + (uint32_t)(r * LDA + c * 8) * 2,
                 Ap + (size_t)(bm + r) * KA + j * KC + c * 8);
        }
#pragma unroll
        for (int i = 0; i < 4; i++) {
            int seg = tid + i * 256;
            int r = seg >> 5, c = seg & 31;
            cp16(st + (uint32_t)(ASZ + r * LDB + c * 8) * 2,
                 Bp + (size_t)(j * KC + r) * Hn + c * 8);
        }
        cp_commit();
    };

    const int warp = tid >> 5, lane = tid & 31;
    const int wm = (warp & 1) * 64;
    const int wn = (warp >> 1) * 64;
    const int lr = lane & 15;
    const int lg8 = (lane >> 4) * 8;

    float acc[4][8][4];
#pragma unroll
    for (int mi = 0; mi < 4; mi++)
#pragma unroll
        for (int ni = 0; ni < 8; ni++)
#pragma unroll
            for (int k = 0; k < 4; k++) acc[mi][ni][k] = 0.f;

    load_chunk(0, 0);
    load_chunk(1, 1);
    load_chunk(2, 2);

    for (int j = 0; j < NC; j++) {
        asm volatile("cp.async.wait_group 2;" ::: "memory");
        __syncthreads();
        if (j + 3 < NC) load_chunk(j + 3, (j + 3) & 3);
        else            cp_commit();

        const uint32_t st = sbase + (uint32_t)((j & 3) * STG) * 2;
#pragma unroll
        for (int ks = 0; ks < KC; ks += 16) {
            uint32_t a[4][4];
#pragma unroll
            for (int mi = 0; mi < 4; mi++)
                ldm_x4(a[mi], st + (uint32_t)((wm + mi * 16 + lr) * LDA + ks + lg8) * 2);
            uint32_t b[4][4];
#pragma unroll
            for (int np = 0; np < 4; np++)
                ldm_x4t(b[np], st + (uint32_t)(ASZ + (ks + lr) * LDB
                                               + wn + np * 16 + lg8) * 2);
#pragma unroll
            for (int mi = 0; mi < 4; mi++)
#pragma unroll
                for (int ni = 0; ni < 8; ni++)
                    mma16816(acc[mi][ni], a[mi], &b[ni >> 1][(ni & 1) * 2]);
        }
    }

    const int g = lane >> 2, tg = (lane & 3) * 2;
#pragma unroll
    for (int mi = 0; mi < 4; mi++) {
#pragma unroll
        for (int ni = 0; ni < 8; ni++) {
            int row = bm + wm + mi * 16 + g;
            int col = wn + ni * 8 + tg;
            float b0 = bias[col], b1 = bias[col + 1];
            *(__half2*)(C + (size_t)row * Hn + col) =
                __floats2half2_rn(acc[mi][ni][0] + b0, acc[mi][ni][1] + b1);
            *(__half2*)(C + (size_t)(row + 8) * Hn + col) =
                __floats2half2_rn(acc[mi][ni][2] + b0, acc[mi][ni][3] + b1);
        }
    }
}

// ---------------------------------------------------------------------------
// FUSED Wo-GEMM + LayerNorm + rel scores:
//   t = ctxP @ Wo + bias; o = LN(relu(t + cur)); cur=o; curP=fp16(o);
//   g_sc scores = o . w~_h.  One CTA = 128 complete rows (same batch b).
// LN staged via smem aliasing the pipeline buffers (2 halves of 64 rows).
// ---------------------------------------------------------------------------
__global__ __launch_bounds__(256, 1)
void hgemm_ln(const __half* __restrict__ Ap, const __half* __restrict__ Bw,
              const float* __restrict__ bias,
              float* __restrict__ cur, float* __restrict__ dup,
              const float* __restrict__ lnw, const float* __restrict__ lnb) {
    extern __shared__ __align__(16) __half smh[];
    const int tid = threadIdx.x;
    const int bm = blockIdx.x * 128;
    const int bB = bm >> 12;                     // batch (128 | 4096)
    const uint32_t sbase = smem_u32(smh);
    float* wts = (float*)((char*)smh + GEMM_SMEM);   // [8][256]

    for (int i = tid; i < 8 * Hn; i += 256)
        wts[i] = g_wtil[(bB * 8 + (i >> 8)) * Hn + (i & 255)];

    auto load_chunk = [&](int j, int s) {
        const uint32_t st = sbase + (uint32_t)(s * STG) * 2;
#pragma unroll
        for (int i = 0; i < 2; i++) {
            int seg = tid + i * 256;
            int r = seg >> 2, c = seg & 3;
            cp16(st + (uint32_t)(r * LDA + c * 8) * 2,
                 Ap + (size_t)(bm + r) * KA + j * KC + c * 8);
        }
#pragma unroll
        for (int i = 0; i < 4; i++) {
            int seg = tid + i * 256;
            int r = seg >> 5, c = seg & 31;
            cp16(st + (uint32_t)(ASZ + r * LDB + c * 8) * 2,
                 Bw + (size_t)(j * KC + r) * Hn + c * 8);
        }
        cp_commit();
    };

    const int warp = tid >> 5, lane = tid & 31;
    const int wm = (warp & 1) * 64;
    const int wn = (warp >> 1) * 64;
    const int lr = lane & 15;
    const int lg8 = (lane >> 4) * 8;

    float acc[4][8][4];
#pragma unroll
    for (int mi = 0; mi < 4; mi++)
#pragma unroll
        for (int ni = 0; ni < 8; ni++)
#pragma unroll
            for (int k = 0; k < 4; k++) acc[mi][ni][k] = 0.f;

    load_chunk(0, 0);
    load_chunk(1, 1);
    load_chunk(2, 2);

    for (int j = 0; j < NC; j++) {
        asm volatile("cp.async.wait_group 2;" ::: "memory");
        __syncthreads();
        if (j + 3 < NC) load_chunk(j + 3, (j + 3) & 3);
        else            cp_commit();

        const uint32_t st = sbase + (uint32_t)((j & 3) * STG) * 2;
#pragma unroll
        for (int ks = 0; ks < KC; ks += 16) {
            uint32_t a[4][4];
#pragma unroll
            for (int mi = 0; mi < 4; mi++)
                ldm_x4(a[mi], st + (uint32_t)((wm + mi * 16 + lr) * LDA + ks + lg8) * 2);
            uint32_t b[4][4];
#pragma unroll
            for (int np = 0; np < 4; np++)
                ldm_x4t(b[np], st + (uint32_t)(ASZ + (ks + lr) * LDB
                                               + wn + np * 16 + lg8) * 2);
#pragma unroll
            for (int mi = 0; mi < 4; mi++)
#pragma unroll
                for (int ni = 0; ni < 8; ni++)
                    mma16816(acc[mi][ni], a[mi], &b[ni >> 1][(ni & 1) * 2]);
        }
    }

    // ---- fused epilogue: two halves of 64 rows via aliased smem ----
    __syncthreads();                       // pipeline smem now dead
    float* sc = (float*)smh;               // [64][SCP] = 67584 B <= 108544
    const int g = lane >> 2, tg = (lane & 3) * 2;

    for (int half = 0; half < 2; half++) {
        if ((warp & 1) == half) {          // warps owning rows half*64..+63
#pragma unroll
            for (int mi = 0; mi < 4; mi++)
#pragma unroll
                for (int ni = 0; ni < 8; ni++) {
                    int rl = mi * 16 + g;
                    int col = wn + ni * 8 + tg;
                    sc[rl * SCP + col]           = acc[mi][ni][0];
                    sc[rl * SCP + col + 1]       = acc[mi][ni][1];
                    sc[(rl + 8) * SCP + col]     = acc[mi][ni][2];
                    sc[(rl + 8) * SCP + col + 1] = acc[mi][ni][3];
                }
        }
        __syncthreads();

        // each warp handles 8 rows of this half
        for (int rr = 0; rr < 8; rr++) {
            int rowl = warp * 8 + rr;
            int row = bm + half * 64 + rowl;
            int l = row & (Ln - 1);
            int k0 = lane * 8;
            size_t base = (size_t)row * Hn + k0;

            float4 c0 = *(const float4*)(cur + base);
            float4 c1 = *(const float4*)(cur + base + 4);
            float4 b0 = *(const float4*)(bias + k0);
            float4 b1 = *(const float4*)(bias + k0 + 4);
            float v[8];
            v[0] = fmaxf(sc[rowl * SCP + k0 + 0] + b0.x + c0.x, 0.f);
            v[1] = fmaxf(sc[rowl * SCP + k0 + 1] + b0.y + c0.y, 0.f);
            v[2] = fmaxf(sc[rowl * SCP + k0 + 2] + b0.z + c0.z, 0.f);
            v[3] = fmaxf(sc[rowl * SCP + k0 + 3] + b0.w + c0.w, 0.f);
            v[4] = fmaxf(sc[rowl * SCP + k0 + 4] + b1.x + c1.x, 0.f);
            v[5] = fmaxf(sc[rowl * SCP + k0 + 5] + b1.y + c1.y, 0.f);
            v[6] = fmaxf(sc[rowl * SCP + k0 + 6] + b1.z + c1.z, 0.f);
            v[7] = fmaxf(sc[rowl * SCP + k0 + 7] + b1.w + c1.w, 0.f);

            float s = 0.f;
#pragma unroll
            for (int j = 0; j < 8; j++) s += v[j];
#pragma unroll
            for (int off = 16; off; off >>= 1)
                s += __shfl_xor_sync(0xffffffffu, s, off);
            float mean = s * (1.f / Hn);

            float s2 = 0.f;
#pragma unroll
            for (int j = 0; j < 8; j++) { float d = v[j] - mean; s2 += d * d; }
#pragma unroll
            for (int off = 16; off; off >>= 1)
                s2 += __shfl_xor_sync(0xffffffffu, s2, off);
            float rstd = rsqrtf(s2 * (1.f / Hn) + LNEPS);

            float4 w0 = *(const float4*)(lnw + k0);
            float4 w1 = *(const float4*)(lnw + k0 + 4);
            float4 lb0 = *(const float4*)(lnb + k0);
            float4 lb1 = *(const float4*)(lnb + k0 + 4);
            float ww[8] = {w0.x, w0.y, w0.z, w0.w, w1.x, w1.y, w1.z, w1.w};
            float bb[8] = {lb0.x, lb0.y, lb0.z, lb0.w, lb1.x, lb1.y, lb1.z, lb1.w};

            float o[8];
            __half hi[8];
#pragma unroll
            for (int j = 0; j < 8; j++) {
                o[j] = ww[j] * (v[j] - mean) * rstd + bb[j];
                hi[j] = __float2half_rn(o[j]);
            }
            float4 oo0 = make_float4(o[0], o[1], o[2], o[3]);
            float4 oo1 = make_float4(o[4], o[5], o[6], o[7]);
            *(float4*)(cur + base)     = oo0;
            *(float4*)(cur + base + 4) = oo1;
            if (dup) {
                *(float4*)(dup + base)     = oo0;
                *(float4*)(dup + base + 4) = oo1;
            }
            *(uint4*)(g_curP + (size_t)row * KA + k0) = *(uint4*)hi;

            // rel scores: s_h = o . w~_h
#pragma unroll
            for (int h = 0; h < 8; h++) {
                float p = 0.f;
#pragma unroll
                for (int j = 0; j < 8; j++) p += o[j] * wts[h * Hn + k0 + j];
#pragma unroll
                for (int off = 16; off; off >>= 1)
                    p += __shfl_xor_sync(0xffffffffu, p, off);
                if (lane == 0)
                    g_sc[(bB * 8 + h) * SCW + 1 + l] = p;
            }
        }
        __syncthreads();
    }
}

// ---------------------------------------------------------------------------
// weight prep: fp16(W) for the 4 sat weights
// ---------------------------------------------------------------------------
__global__ void wprep_kernel(const float* W0, const float* W1, const float* W2,
                             const float* W3) {
    const float* Ws[4] = {W0, W1, W2, W3};
    int wi = blockIdx.y;
    int k = blockIdx.x, n = threadIdx.x;
    g_BT[(size_t)wi * Hn * Hn + (size_t)k * Hn + n] =
        __float2half_rn(Ws[wi][(size_t)k * Hn + n]);
}

// x -> cur (fp32) + curP (fp16)
__global__ void splitcopy_kernel(const float* __restrict__ x) {
    int t = blockIdx.x * blockDim.x + threadIdx.x;   // Mn*Hn/8
    int row = t >> 5;
    int k0 = (t & 31) * 8;
    const float4* src = (const float4*)(x + (size_t)row * Hn + k0);
    float4* dst = (float4*)(g_cur + (size_t)row * Hn + k0);
    float4 v0 = src[0], v1 = src[1];
    dst[0] = v0; dst[1] = v1;
    __half hi[8];
    float vv[8] = {v0.x, v0.y, v0.z, v0.w, v1.x, v1.y, v1.z, v1.w};
#pragma unroll
    for (int j = 0; j < 8; j++) hi[j] = __float2half_rn(vv[j]);
    *(uint4*)(g_curP + (size_t)row * KA + k0) = *(uint4*)hi;
}

// partial column sums of x over L (stage 1 of mean)
__global__ void meanpart_kernel(const float* __restrict__ x) {
    int c = blockIdx.x, b = blockIdx.y, h = threadIdx.x;
    const float* p = x + ((size_t)b * Ln + c * 256) * Hn + h;
    float s = 0.f;
    for (int l = 0; l < 256; l++) s += p[(size_t)l * Hn];
    g_cpart[(b * 16 + c) * Hn + h] = s;
}

// ---------------------------------------------------------------------------
// center projections, 8-way k-split: grid (3*Bn, 8).
// ---------------------------------------------------------------------------
__global__ void proj_center_kernel(
    const float* __restrict__ satWk, const float* __restrict__ satbk,
    const float* __restrict__ satWv, const float* __restrict__ satbv,
    const float* __restrict__ relWq, const float* __restrict__ relbq,
    int use_cpart) {
    __shared__ float c[32];
    int b   = blockIdx.x % Bn;
    int sel = blockIdx.x / Bn;
    int ks  = blockIdx.y;
    int n   = threadIdx.x;
    int k0  = ks * 32;
    if (n < 32) {
        int k = k0 + n;
        float v;
        if (use_cpart) {
            float s = 0.f;
#pragma unroll
            for (int i = 0; i < 16; i++) s += g_cpart[(b * 16 + i) * Hn + k];
            v = s * (1.f / Ln);
            if (sel == 0) g_center[b * Hn + k] = v;
        } else {
            v = g_center[b * Hn + k];
        }
        c[n] = v;
    }
    __syncthreads();
    const float* W; const float* bi;
    switch (sel) {
        case 0: W = satWk; bi = satbk; break;
        case 1: W = satWv; bi = satbv; break;
        default: W = relWq; bi = relbq; break;
    }
    float s = 0.f;
#pragma unroll
    for (int k = 0; k < 32; k++) s += c[k] * W[(size_t)(k0 + k) * Hn + n];
    if (ks == 0) s += bi[n];
    g_cproj[ks][sel][b * Hn + n] = s;
}

// ---------------------------------------------------------------------------
// rel: w~_bh[k] = SCALE * sum_d Wrk[k][h*32+d] * qrel_bh[d]; s0 = center.w~
// ---------------------------------------------------------------------------
__global__ __launch_bounds__(256)
void rel_wtil_kernel(const float* __restrict__ relWk) {
    __shared__ float q[HDn];
    __shared__ float red[8];
    int bh = blockIdx.x;
    int b = bh >> 3, h = bh & 7;
    int t = threadIdx.x;
    if (t < HDn) {
        int i = b * Hn + h * HDn + t;
        float s = 0.f;
#pragma unroll
        for (int pp = 0; pp < 8; pp++) s += g_cproj[pp][2][i];
        q[t] = s;
    }
    __syncthreads();
    float w = 0.f;
#pragma unroll 8
    for (int d = 0; d < HDn; d++)
        w += relWk[(size_t)t * Hn + h * HDn + d] * q[d];
    w *= SCALE;
    g_wtil[bh * Hn + t] = w;

    // s0 = center . w~
    float c = g_center[b * Hn + t] * w;
#pragma unroll
    for (int off = 16; off; off >>= 1) c += __shfl_xor_sync(0xffffffffu, c, off);
    if ((t & 31) == 0) red[t >> 5] = c;
    __syncthreads();
    if (t == 0) {
        float tot = 0.f;
#pragma unroll
        for (int i = 0; i < 8; i++) tot += red[i];
        g_sc[bh * SCW] = tot;
    }
}

// ---------------------------------------------------------------------------
// satellite attention (fp16 operands) -> writes ctxP (fp16)
// ---------------------------------------------------------------------------
__global__ __launch_bounds__(256)
void sat_attn_kernel(const __half* __restrict__ Kc, const __half* __restrict__ Vc) {
    int token = blockIdx.x;
    int b = token >> 12;
    int l = token & (Ln - 1);
    int h = threadIdx.x >> 5;
    int d = threadIdx.x & 31;
    int col = h * HDn + d;

    size_t ic   = (size_t)token * Hn + col;
    int lb = (l + 1) & (Ln - 1);
    int la = (l == 0) ? (Ln - 1) : 0;
    size_t ibe  = ((size_t)(b * Ln + lb)) * Hn + col;
    size_t iaf  = ((size_t)(b * Ln + la)) * Hn + col;
    int icen = b * Hn + col;

    float kcen = 0.f, vcen = 0.f;
#pragma unroll
    for (int pp = 0; pp < 8; pp++) {
        kcen += g_cproj[pp][0][icen];
        vcen += g_cproj[pp][1][icen];
    }

    float q  = __half2float(g_Qh[ic]);
    float s0 = q * __half2float(Kc[ibe]);
    float s1 = q * __half2float(Kc[ic]);
    float s2 = q * __half2float(Kc[iaf]);
    float s3 = q * __half2float(g_Kxh[ic]);
    float s4 = q * kcen;
#pragma unroll
    for (int off = 16; off; off >>= 1) {
        s0 += __shfl_xor_sync(0xffffffffu, s0, off);
        s1 += __shfl_xor_sync(0xffffffffu, s1, off);
        s2 += __shfl_xor_sync(0xffffffffu, s2, off);
        s3 += __shfl_xor_sync(0xffffffffu, s3, off);
        s4 += __shfl_xor_sync(0xffffffffu, s4, off);
    }
    s0 *= SCALE; s1 *= SCALE; s2 *= SCALE; s3 *= SCALE; s4 *= SCALE;
    float mx = fmaxf(fmaxf(fmaxf(s0, s1), fmaxf(s2, s3)), s4);
    float e0 = expf(s0 - mx), e1 = expf(s1 - mx), e2 = expf(s2 - mx);
    float e3 = expf(s3 - mx), e4 = expf(s4 - mx);
    float inv = 1.f / (e0 + e1 + e2 + e3 + e4);
    float ctx = (e0 * __half2float(Vc[ibe]) + e1 * __half2float(Vc[ic]) +
                 e2 * __half2float(Vc[iaf]) + e3 * __half2float(g_Vxh[ic]) +
                 e4 * vcen) * inv;

    g_ctxP[(size_t)token * KA + col] = __float2half_rn(ctx);
}

// ---------------------------------------------------------------------------
// rel softmax stats: per bh, max + sum-exp over 4097 scores
// ---------------------------------------------------------------------------
__global__ __launch_bounds__(256)
void rel_stat_kernel() {
    __shared__ float red[8];
    int bh = blockIdx.x;
    int t = threadIdx.x;
    const float* sc = g_sc + bh * SCW;

    float m = -1e30f;
    for (int j = t; j <= Ln; j += 256) m = fmaxf(m, sc[j]);
#pragma unroll
    for (int off = 16; off; off >>= 1)
        m = fmaxf(m, __shfl_xor_sync(0xffffffffu, m, off));
    if ((t & 31) == 0) red[t >> 5] = m;
    __syncthreads();
    float mm = -1e30f;
#pragma unroll
    for (int i = 0; i < 8; i++) mm = fmaxf(mm, red[i]);
    __syncthreads();

    float z = 0.f;
    for (int j = t; j <= Ln; j += 256) z += expf(sc[j] - mm);
#pragma unroll
    for (int off = 16; off; off >>= 1) z += __shfl_xor_sync(0xffffffffu, z, off);
    if ((t & 31) == 0) red[t >> 5] = z;
    __syncthreads();
    if (t == 0) {
        float tot = 0.f;
#pragma unroll
        for (int i = 0; i < 8; i++) tot += red[i];
        g_pm[bh] = mm;
        g_ps[bh] = tot;
    }
}

// ---------------------------------------------------------------------------
// rel weighted row-sum: grid (Bn, NSP=32); 128 keys per chunk.
// ---------------------------------------------------------------------------
__global__ __launch_bounds__(256)
void rel_wsum_kernel() {
    __shared__ float p[8][128];
    __shared__ float mz[16];
    int b = blockIdx.x, sp = blockIdx.y;
    int t = threadIdx.x;
    if (t < 8)       mz[t] = g_pm[b * 8 + t];
    else if (t < 16) mz[t] = 1.f / g_ps[b * 8 + (t - 8)];
    __syncthreads();
    for (int i = t; i < 8 * 128; i += 256) {
        int hh = i >> 7, jj = i & 127;
        p[hh][jj] = expf(g_sc[(b * 8 + hh) * SCW + 1 + sp * 128 + jj] - mz[hh])
                    * mz[8 + hh];
    }
    __syncthreads();

    int h = t >> 5, kg = t & 31;
    float a0x = 0.f, a0y = 0.f, a0z = 0.f, a0w = 0.f;
    float a1x = 0.f, a1y = 0.f, a1z = 0.f, a1w = 0.f;
    for (int jj = 0; jj < 128; jj++) {
        size_t row = (size_t)(b * Ln + sp * 128 + jj) * Hn + kg * 8;
        float4 c0 = *(const float4*)(g_cur + row);
        float4 c1 = *(const float4*)(g_cur + row + 4);
        float pp = p[h][jj];
        a0x += pp * c0.x; a0y += pp * c0.y; a0z += pp * c0.z; a0w += pp * c0.w;
        a1x += pp * c1.x; a1y += pp * c1.y; a1z += pp * c1.z; a1w += pp * c1.w;
    }
    size_t o = (size_t)((b * NSP + sp) * 8 + h) * Hn + kg * 8;
    *(float4*)(g_upart + o)     = make_float4(a0x, a0y, a0z, a0w);
    *(float4*)(g_upart + o + 4) = make_float4(a1x, a1y, a1z, a1w);
}

// ---------------------------------------------------------------------------
// rel epilogue: u = sum_sp upart + p0*center; cx = u@Wrv + bv;
// dst = LN(relu(cx@Wo + bo + center)); also updates g_center
// ---------------------------------------------------------------------------
__global__ __launch_bounds__(256)
void rel_epi_kernel(const float* __restrict__ Wrv, const float* __restrict__ brv,
                    const float* __restrict__ Wo, const float* __restrict__ bo,
                    const float* __restrict__ lnw, const float* __restrict__ lnb,
                    float* __restrict__ dst) {
    __shared__ float u[8][Hn];
    __shared__ float cx[Hn];
    __shared__ float red[8];
    int b = blockIdx.x;
    int n = threadIdx.x;

    float ctr = g_center[b * Hn + n];
#pragma unroll
    for (int h = 0; h < 8; h++) {
        float s = 0.f;
        for (int sp = 0; sp < NSP; sp++)
            s += g_upart[(size_t)((b * NSP + sp) * 8 + h) * Hn + n];
        float p0 = expf(g_sc[(b * 8 + h) * SCW] - g_pm[b * 8 + h]) / g_ps[b * 8 + h];
        u[h][n] = s + p0 * ctr;
    }
    __syncthreads();

    int h = n >> 5;
    float cval = 0.f;
#pragma unroll 8
    for (int k = 0; k < Hn; k++) cval += u[h][k] * Wrv[(size_t)k * Hn + n];
    cx[n] = cval + brv[n];
    __syncthreads();

    float s = 0.f;
#pragma unroll 8
    for (int k = 0; k < Hn; k++) s += cx[k] * Wo[(size_t)k * Hn + n];
    float v = fmaxf(s + bo[n] + ctr, 0.f);

    float r = v;
#pragma unroll
    for (int off = 16; off; off >>= 1) r += __shfl_xor_sync(0xffffffffu, r, off);
    if ((n & 31) == 0) red[n >> 5] = r;
    __syncthreads();
    float tot = 0.f;
#pragma unroll
    for (int i = 0; i < 8; i++) tot += red[i];
    float mean = tot * (1.f / Hn);
    __syncthreads();

    float dv = v - mean;
    float r2 = dv * dv;
#pragma unroll
    for (int off = 16; off; off >>= 1) r2 += __shfl_xor_sync(0xffffffffu, r2, off);
    if ((n & 31) == 0) red[n >> 5] = r2;
    __syncthreads();
    tot = 0.f;
#pragma unroll
    for (int i = 0; i < 8; i++) tot += red[i];
    float var = tot * (1.f / Hn);

    float o = lnw[n] * dv * rsqrtf(var + LNEPS) + lnb[n];
    g_center[b * Hn + n] = o;
    dst[b * Hn + n] = o;
}

// ---------------------------------------------------------------------------
extern "C" void kernel_launch(void* const* d_in, const int* in_sizes, int n_in,
                              void* d_out, int out_size) {
    const float* x     = (const float*)d_in[0];
    const float* satWq = (const float*)d_in[1];  const float* satbq = (const float*)d_in[2];
    const float* satWk = (const float*)d_in[3];  const float* satbk = (const float*)d_in[4];
    const float* satWv = (const float*)d_in[5];  const float* satbv = (const float*)d_in[6];
    const float* satWo = (const float*)d_in[7];  const float* satbo = (const float*)d_in[8];
    const float* relWq = (const float*)d_in[9];  const float* relbq = (const float*)d_in[10];
    const float* relWk = (const float*)d_in[11]; const float* relbk = (const float*)d_in[12];
    const float* relWv = (const float*)d_in[13]; const float* relbv = (const float*)d_in[14];
    const float* relWo = (const float*)d_in[15]; const float* relbo = (const float*)d_in[16];
    const float* slnw  = (const float*)d_in[17]; const float* slnb  = (const float*)d_in[18];
    const float* rlnw  = (const float*)d_in[19]; const float* rlnb  = (const float*)d_in[20];
    float* out = (float*)d_out;
    (void)relbk;   // key bias cancels in softmax

    float *cur, *center;
    __half *curP, *ctxP, *BT, *Qh, *Kch, *Vch, *Kxh, *Vxh;
    cudaGetSymbolAddress((void**)&cur,  g_cur);
    cudaGetSymbolAddress((void**)&curP, g_curP);
    cudaGetSymbolAddress((void**)&ctxP, g_ctxP);
    cudaGetSymbolAddress((void**)&BT,   g_BT);
    cudaGetSymbolAddress((void**)&center, g_center);
    cudaGetSymbolAddress((void**)&Qh,  g_Qh);
    cudaGetSymbolAddress((void**)&Kch, g_Kch);
    cudaGetSymbolAddress((void**)&Vch, g_Vch);
    cudaGetSymbolAddress((void**)&Kxh, g_Kxh);
    cudaGetSymbolAddress((void**)&Vxh, g_Vxh);

    cudaFuncSetAttribute(hgemm_qkv, cudaFuncAttributeMaxDynamicSharedMemorySize,
                         GEMM_SMEM);
    cudaFuncSetAttribute(hgemm_ln, cudaFuncAttributeMaxDynamicSharedMemorySize,
                         LN_SMEM);

    // fp16 weights: 0 satWq, 1 satWk, 2 satWv, 3 satWo
    wprep_kernel<<<dim3(Hn, 4), Hn>>>(satWq, satWk, satWv, satWo);

    splitcopy_kernel<<<Mn * Hn / 8 / 256, 256>>>(x);
    meanpart_kernel<<<dim3(16, Bn), Hn>>>(x);

    const __half* Wq = BT + (size_t)0 * Hn * Hn;
    const __half* Wk = BT + (size_t)1 * Hn * Hn;
    const __half* Wv = BT + (size_t)2 * Hn * Hn;
    const __half* Wo = BT + (size_t)3 * Hn * Hn;

    for (int it = 0; it < 2; it++) {
        proj_center_kernel<<<dim3(3 * Bn, 8), Hn>>>(
            satWk, satbk, satWv, satbv, relWq, relbq, it == 0 ? 1 : 0);
        rel_wtil_kernel<<<Bn * NHn, Hn>>>(relWk);   // before GEMMs: hgemm_ln needs w~
        // iter 0: cur == x, so K/V projections double as loop-invariant Kx/Vx
        __half* Kdst = (it == 0) ? Kxh : Kch;
        __half* Vdst = (it == 0) ? Vxh : Vch;
        hgemm_qkv<<<dim3(Mn / 128, 3), 256, GEMM_SMEM>>>(
            curP, Wq, Wk, Wv, satbq, satbk, satbv, Qh, Kdst, Vdst);
        sat_attn_kernel<<<Mn, 256>>>(Kdst, Vdst);
        // fused Wo-GEMM + LN + rel scores (replaces hgemm + ln_rows)
        float* dup = (it == 0) ? (float*)nullptr : out;
        hgemm_ln<<<Mn / 128, 256, LN_SMEM>>>(ctxP, Wo, satbo, cur, dup, slnw, slnb);

        rel_stat_kernel<<<Bn * NHn, 256>>>();
        rel_wsum_kernel<<<dim3(Bn, NSP), 256>>>();
        float* cdst = (it == 0) ? center : (out + (size_t)Mn * Hn);
        rel_epi_kernel<<<Bn, Hn>>>(relWv, relbv, relWo, relbo, rlnw, rlnb, cdst);
    }
}

// round 17
// speedup vs baseline: 1.5820x; 1.0727x over previous
#include <cuda_runtime.h>
#include <cuda_fp16.h>
#include <math.h>
#include <stdint.h>

// ---------------------------------------------------------------------------
// StarTransformerLayer, GB300 (compute_103 -> mma.sync path).
// B=8, L=4096, H=256, NH=8, HD=32, 2 iterations.
// R17: sat_attn restructured for full-width (128B/warp) loads:
//   2 tokens/block, 16 lanes/head, __half2 per thread.
// R16 carried: fused Wo-GEMM+LN+rel-scores; fp16 attention operands (R15);
// GEMM-free rel attention (R11); fp16 GEMMs (R8). Best: 604.7 us.
// ---------------------------------------------------------------------------

namespace {
constexpr int Bn  = 8;
constexpr int Ln  = 4096;
constexpr int Hn  = 256;
constexpr int NHn = 8;
constexpr int HDn = 32;
constexpr int Mn  = Bn * Ln;          // 32768
constexpr int KA  = 256;              // fp16 A columns
constexpr int SCW = 4128;             // score row stride (4097 used)
constexpr int NSP = 32;               // wsum chunks (128 keys each)
constexpr float SCALE = 0.17677669529663688f;   // 1/sqrt(32)
constexpr float LNEPS = 1e-12f;
// GEMM tiling
constexpr int KC   = 32;
constexpr int NC   = KA / KC;         // 8 chunks
constexpr int LDA  = 40;              // 32 + 8 pad (halfs)
constexpr int LDB  = 264;             // 256 + 8 pad (halfs)
constexpr int ASZ  = 128 * LDA;       // 5120 halfs
constexpr int BSZ  = KC * LDB;        // 8448 halfs
constexpr int STG  = ASZ + BSZ;       // 13568 halfs
constexpr int GEMM_SMEM = STG * 2 * 4;   // 108544 bytes (4 stages)
// fused LN epilogue
constexpr int SCP = 264;                 // padded row (floats)
constexpr int LN_SMEM = GEMM_SMEM + 8 * Hn * 4;   // 116736
}

// ---- scratch (device globals) ---------------------------------------------
__device__ float  g_cur [Mn * Hn];
__device__ __align__(16) __half g_curP[(size_t)Mn * KA];
__device__ __align__(16) __half g_ctxP[(size_t)Mn * KA];
__device__ __align__(16) __half g_BT  [4 * (size_t)Hn * Hn];
// fp16 attention operands (sat_attn consumers only)
__device__ __align__(16) __half g_Qh [(size_t)Mn * Hn];
__device__ __align__(16) __half g_Kch[(size_t)Mn * Hn];
__device__ __align__(16) __half g_Vch[(size_t)Mn * Hn];
__device__ __align__(16) __half g_Kxh[(size_t)Mn * Hn];
__device__ __align__(16) __half g_Vxh[(size_t)Mn * Hn];

__device__ float g_center[Bn * Hn];
// center projections, 8 k-partials: [ks][sel][b*Hn+n]; sel 0=Kcen 1=Vcen 2=Qrel
__device__ float g_cproj[8][3][Bn * Hn];
__device__ float g_cpart[Bn * 16 * Hn];

// rel attention scratch
__device__ float g_wtil[64 * Hn];            // per (b,h): w~ (includes SCALE)
__device__ float g_sc  [64 * SCW];           // scores, jidx 0..4096
__device__ float g_pm  [64];                 // per-bh max
__device__ float g_ps  [64];                 // per-bh sum-exp
__device__ float g_upart[(size_t)Bn * NSP * NHn * Hn];   // partial wsums

// ---------------------------------------------------------------------------
// helpers
// ---------------------------------------------------------------------------
__device__ __forceinline__ uint32_t smem_u32(const void* p) {
    uint32_t a;
    asm("{ .reg .u64 t; cvta.to.shared.u64 t, %1; cvt.u32.u64 %0, t; }"
        : "=r"(a) : "l"(p));
    return a;
}
__device__ __forceinline__ void cp16(uint32_t s, const void* g) {
    asm volatile("cp.async.cg.shared.global [%0], [%1], 16;" :: "r"(s), "l"(g));
}
__device__ __forceinline__ void cp_commit() {
    asm volatile("cp.async.commit_group;" ::: "memory");
}
__device__ __forceinline__ void ldm_x4(uint32_t* r, uint32_t a) {
    asm volatile("ldmatrix.sync.aligned.m8n8.x4.shared.b16 {%0,%1,%2,%3}, [%4];"
                 : "=r"(r[0]), "=r"(r[1]), "=r"(r[2]), "=r"(r[3]) : "r"(a));
}
__device__ __forceinline__ void ldm_x4t(uint32_t* r, uint32_t a) {
    asm volatile("ldmatrix.sync.aligned.m8n8.x4.trans.shared.b16 {%0,%1,%2,%3}, [%4];"
                 : "=r"(r[0]), "=r"(r[1]), "=r"(r[2]), "=r"(r[3]) : "r"(a));
}
__device__ __forceinline__ void mma16816(float* c, const uint32_t* a,
                                         const uint32_t* b) {
    asm volatile(
        "mma.sync.aligned.m16n8k16.row.col.f32.f16.f16.f32 "
        "{%0,%1,%2,%3}, {%4,%5,%6,%7}, {%8,%9}, {%0,%1,%2,%3};"
        : "+f"(c[0]), "+f"(c[1]), "+f"(c[2]), "+f"(c[3])
        : "r"(a[0]), "r"(a[1]), "r"(a[2]), "r"(a[3]), "r"(b[0]), "r"(b[1]));
}

// ---------------------------------------------------------------------------
// QKV GEMM: C[M,256] = A[M,256](fp16) @ B[256,256](fp16) + bias, fp16 out.
// ---------------------------------------------------------------------------
__global__ __launch_bounds__(256, 1)
void hgemm_qkv(const __half* __restrict__ Ap,
               const __half* B0, const __half* B1, const __half* B2,
               const float* bias0, const float* bias1, const float* bias2,
               __half* C0, __half* C1, __half* C2) {
    extern __shared__ __align__(16) __half smh[];
    const int tid = threadIdx.x;
    const int bm = blockIdx.x * 128;
    const int wsel = blockIdx.y;
    const __half* Bp  = (wsel == 0) ? B0 : (wsel == 1) ? B1 : B2;
    const float*  bias = (wsel == 0) ? bias0 : (wsel == 1) ? bias1 : bias2;
    __half*       C   = (wsel == 0) ? C0 : (wsel == 1) ? C1 : C2;
    const uint32_t sbase = smem_u32(smh);

    auto load_chunk = [&](int j, int s) {
        const uint32_t st = sbase + (uint32_t)(s * STG) * 2;
#pragma unroll
        for (int i = 0; i < 2; i++) {
            int seg = tid + i * 256;
            int r = seg >> 2, c = seg & 3;
            cp16(st + (uint32_t)(r * LDA + c * 8) * 2,
                 Ap + (size_t)(bm + r) * KA + j * KC + c * 8);
        }
#pragma unroll
        for (int i = 0; i < 4; i++) {
            int seg = tid + i * 256;
            int r = seg >> 5, c = seg & 31;
            cp16(st + (uint32_t)(ASZ + r * LDB + c * 8) * 2,
                 Bp + (size_t)(j * KC + r) * Hn + c * 8);
        }
        cp_commit();
    };

    const int warp = tid >> 5, lane = tid & 31;
    const int wm = (warp & 1) * 64;
    const int wn = (warp >> 1) * 64;
    const int lr = lane & 15;
    const int lg8 = (lane >> 4) * 8;

    float acc[4][8][4];
#pragma unroll
    for (int mi = 0; mi < 4; mi++)
#pragma unroll
        for (int ni = 0; ni < 8; ni++)
#pragma unroll
            for (int k = 0; k < 4; k++) acc[mi][ni][k] = 0.f;

    load_chunk(0, 0);
    load_chunk(1, 1);
    load_chunk(2, 2);

    for (int j = 0; j < NC; j++) {
        asm volatile("cp.async.wait_group 2;" ::: "memory");
        __syncthreads();
        if (j + 3 < NC) load_chunk(j + 3, (j + 3) & 3);
        else            cp_commit();

        const uint32_t st = sbase + (uint32_t)((j & 3) * STG) * 2;
#pragma unroll
        for (int ks = 0; ks < KC; ks += 16) {
            uint32_t a[4][4];
#pragma unroll
            for (int mi = 0; mi < 4; mi++)
                ldm_x4(a[mi], st + (uint32_t)((wm + mi * 16 + lr) * LDA + ks + lg8) * 2);
            uint32_t b[4][4];
#pragma unroll
            for (int np = 0; np < 4; np++)
                ldm_x4t(b[np], st + (uint32_t)(ASZ + (ks + lr) * LDB
                                               + wn + np * 16 + lg8) * 2);
#pragma unroll
            for (int mi = 0; mi < 4; mi++)
#pragma unroll
                for (int ni = 0; ni < 8; ni++)
                    mma16816(acc[mi][ni], a[mi], &b[ni >> 1][(ni & 1) * 2]);
        }
    }

    const int g = lane >> 2, tg = (lane & 3) * 2;
#pragma unroll
    for (int mi = 0; mi < 4; mi++) {
#pragma unroll
        for (int ni = 0; ni < 8; ni++) {
            int row = bm + wm + mi * 16 + g;
            int col = wn + ni * 8 + tg;
            float b0 = bias[col], b1 = bias[col + 1];
            *(__half2*)(C + (size_t)row * Hn + col) =
                __floats2half2_rn(acc[mi][ni][0] + b0, acc[mi][ni][1] + b1);
            *(__half2*)(C + (size_t)(row + 8) * Hn + col) =
                __floats2half2_rn(acc[mi][ni][2] + b0, acc[mi][ni][3] + b1);
        }
    }
}

// ---------------------------------------------------------------------------
// FUSED Wo-GEMM + LayerNorm + rel scores (R16).
// ---------------------------------------------------------------------------
__global__ __launch_bounds__(256, 1)
void hgemm_ln(const __half* __restrict__ Ap, const __half* __restrict__ Bw,
              const float* __restrict__ bias,
              float* __restrict__ cur, float* __restrict__ dup,
              const float* __restrict__ lnw, const float* __restrict__ lnb) {
    extern __shared__ __align__(16) __half smh[];
    const int tid = threadIdx.x;
    const int bm = blockIdx.x * 128;
    const int bB = bm >> 12;
    const uint32_t sbase = smem_u32(smh);
    float* wts = (float*)((char*)smh + GEMM_SMEM);

    for (int i = tid; i < 8 * Hn; i += 256)
        wts[i] = g_wtil[(bB * 8 + (i >> 8)) * Hn + (i & 255)];

    auto load_chunk = [&](int j, int s) {
        const uint32_t st = sbase + (uint32_t)(s * STG) * 2;
#pragma unroll
        for (int i = 0; i < 2; i++) {
            int seg = tid + i * 256;
            int r = seg >> 2, c = seg & 3;
            cp16(st + (uint32_t)(r * LDA + c * 8) * 2,
                 Ap + (size_t)(bm + r) * KA + j * KC + c * 8);
        }
#pragma unroll
        for (int i = 0; i < 4; i++) {
            int seg = tid + i * 256;
            int r = seg >> 5, c = seg & 31;
            cp16(st + (uint32_t)(ASZ + r * LDB + c * 8) * 2,
                 Bw + (size_t)(j * KC + r) * Hn + c * 8);
        }
        cp_commit();
    };

    const int warp = tid >> 5, lane = tid & 31;
    const int wm = (warp & 1) * 64;
    const int wn = (warp >> 1) * 64;
    const int lr = lane & 15;
    const int lg8 = (lane >> 4) * 8;

    float acc[4][8][4];
#pragma unroll
    for (int mi = 0; mi < 4; mi++)
#pragma unroll
        for (int ni = 0; ni < 8; ni++)
#pragma unroll
            for (int k = 0; k < 4; k++) acc[mi][ni][k] = 0.f;

    load_chunk(0, 0);
    load_chunk(1, 1);
    load_chunk(2, 2);

    for (int j = 0; j < NC; j++) {
        asm volatile("cp.async.wait_group 2;" ::: "memory");
        __syncthreads();
        if (j + 3 < NC) load_chunk(j + 3, (j + 3) & 3);
        else            cp_commit();

        const uint32_t st = sbase + (uint32_t)((j & 3) * STG) * 2;
#pragma unroll
        for (int ks = 0; ks < KC; ks += 16) {
            uint32_t a[4][4];
#pragma unroll
            for (int mi = 0; mi < 4; mi++)
                ldm_x4(a[mi], st + (uint32_t)((wm + mi * 16 + lr) * LDA + ks + lg8) * 2);
            uint32_t b[4][4];
#pragma unroll
            for (int np = 0; np < 4; np++)
                ldm_x4t(b[np], st + (uint32_t)(ASZ + (ks + lr) * LDB
                                               + wn + np * 16 + lg8) * 2);
#pragma unroll
            for (int mi = 0; mi < 4; mi++)
#pragma unroll
                for (int ni = 0; ni < 8; ni++)
                    mma16816(acc[mi][ni], a[mi], &b[ni >> 1][(ni & 1) * 2]);
        }
    }

    __syncthreads();
    float* sc = (float*)smh;
    const int g = lane >> 2, tg = (lane & 3) * 2;

    for (int half = 0; half < 2; half++) {
        if ((warp & 1) == half) {
#pragma unroll
            for (int mi = 0; mi < 4; mi++)
#pragma unroll
                for (int ni = 0; ni < 8; ni++) {
                    int rl = mi * 16 + g;
                    int col = wn + ni * 8 + tg;
                    sc[rl * SCP + col]           = acc[mi][ni][0];
                    sc[rl * SCP + col + 1]       = acc[mi][ni][1];
                    sc[(rl + 8) * SCP + col]     = acc[mi][ni][2];
                    sc[(rl + 8) * SCP + col + 1] = acc[mi][ni][3];
                }
        }
        __syncthreads();

        for (int rr = 0; rr < 8; rr++) {
            int rowl = warp * 8 + rr;
            int row = bm + half * 64 + rowl;
            int l = row & (Ln - 1);
            int k0 = lane * 8;
            size_t base = (size_t)row * Hn + k0;

            float4 c0 = *(const float4*)(cur + base);
            float4 c1 = *(const float4*)(cur + base + 4);
            float4 b0 = *(const float4*)(bias + k0);
            float4 b1 = *(const float4*)(bias + k0 + 4);
            float v[8];
            v[0] = fmaxf(sc[rowl * SCP + k0 + 0] + b0.x + c0.x, 0.f);
            v[1] = fmaxf(sc[rowl * SCP + k0 + 1] + b0.y + c0.y, 0.f);
            v[2] = fmaxf(sc[rowl * SCP + k0 + 2] + b0.z + c0.z, 0.f);
            v[3] = fmaxf(sc[rowl * SCP + k0 + 3] + b0.w + c0.w, 0.f);
            v[4] = fmaxf(sc[rowl * SCP + k0 + 4] + b1.x + c1.x, 0.f);
            v[5] = fmaxf(sc[rowl * SCP + k0 + 5] + b1.y + c1.y, 0.f);
            v[6] = fmaxf(sc[rowl * SCP + k0 + 6] + b1.z + c1.z, 0.f);
            v[7] = fmaxf(sc[rowl * SCP + k0 + 7] + b1.w + c1.w, 0.f);

            float s = 0.f;
#pragma unroll
            for (int j = 0; j < 8; j++) s += v[j];
#pragma unroll
            for (int off = 16; off; off >>= 1)
                s += __shfl_xor_sync(0xffffffffu, s, off);
            float mean = s * (1.f / Hn);

            float s2 = 0.f;
#pragma unroll
            for (int j = 0; j < 8; j++) { float d = v[j] - mean; s2 += d * d; }
#pragma unroll
            for (int off = 16; off; off >>= 1)
                s2 += __shfl_xor_sync(0xffffffffu, s2, off);
            float rstd = rsqrtf(s2 * (1.f / Hn) + LNEPS);

            float4 w0 = *(const float4*)(lnw + k0);
            float4 w1 = *(const float4*)(lnw + k0 + 4);
            float4 lb0 = *(const float4*)(lnb + k0);
            float4 lb1 = *(const float4*)(lnb + k0 + 4);
            float ww[8] = {w0.x, w0.y, w0.z, w0.w, w1.x, w1.y, w1.z, w1.w};
            float bb[8] = {lb0.x, lb0.y, lb0.z, lb0.w, lb1.x, lb1.y, lb1.z, lb1.w};

            float o[8];
            __half hi[8];
#pragma unroll
            for (int j = 0; j < 8; j++) {
                o[j] = ww[j] * (v[j] - mean) * rstd + bb[j];
                hi[j] = __float2half_rn(o[j]);
            }
            float4 oo0 = make_float4(o[0], o[1], o[2], o[3]);
            float4 oo1 = make_float4(o[4], o[5], o[6], o[7]);
            *(float4*)(cur + base)     = oo0;
            *(float4*)(cur + base + 4) = oo1;
            if (dup) {
                *(float4*)(dup + base)     = oo0;
                *(float4*)(dup + base + 4) = oo1;
            }
            *(uint4*)(g_curP + (size_t)row * KA + k0) = *(uint4*)hi;

#pragma unroll
            for (int h = 0; h < 8; h++) {
                float p = 0.f;
#pragma unroll
                for (int j = 0; j < 8; j++) p += o[j] * wts[h * Hn + k0 + j];
#pragma unroll
                for (int off = 16; off; off >>= 1)
                    p += __shfl_xor_sync(0xffffffffu, p, off);
                if (lane == 0)
                    g_sc[(bB * 8 + h) * SCW + 1 + l] = p;
            }
        }
        __syncthreads();
    }
}

// ---------------------------------------------------------------------------
// weight prep: fp16(W) for the 4 sat weights
// ---------------------------------------------------------------------------
__global__ void wprep_kernel(const float* W0, const float* W1, const float* W2,
                             const float* W3) {
    const float* Ws[4] = {W0, W1, W2, W3};
    int wi = blockIdx.y;
    int k = blockIdx.x, n = threadIdx.x;
    g_BT[(size_t)wi * Hn * Hn + (size_t)k * Hn + n] =
        __float2half_rn(Ws[wi][(size_t)k * Hn + n]);
}

// x -> cur (fp32) + curP (fp16)
__global__ void splitcopy_kernel(const float* __restrict__ x) {
    int t = blockIdx.x * blockDim.x + threadIdx.x;
    int row = t >> 5;
    int k0 = (t & 31) * 8;
    const float4* src = (const float4*)(x + (size_t)row * Hn + k0);
    float4* dst = (float4*)(g_cur + (size_t)row * Hn + k0);
    float4 v0 = src[0], v1 = src[1];
    dst[0] = v0; dst[1] = v1;
    __half hi[8];
    float vv[8] = {v0.x, v0.y, v0.z, v0.w, v1.x, v1.y, v1.z, v1.w};
#pragma unroll
    for (int j = 0; j < 8; j++) hi[j] = __float2half_rn(vv[j]);
    *(uint4*)(g_curP + (size_t)row * KA + k0) = *(uint4*)hi;
}

// partial column sums of x over L (stage 1 of mean)
__global__ void meanpart_kernel(const float* __restrict__ x) {
    int c = blockIdx.x, b = blockIdx.y, h = threadIdx.x;
    const float* p = x + ((size_t)b * Ln + c * 256) * Hn + h;
    float s = 0.f;
    for (int l = 0; l < 256; l++) s += p[(size_t)l * Hn];
    g_cpart[(b * 16 + c) * Hn + h] = s;
}

// ---------------------------------------------------------------------------
// center projections, 8-way k-split: grid (3*Bn, 8).
// ---------------------------------------------------------------------------
__global__ void proj_center_kernel(
    const float* __restrict__ satWk, const float* __restrict__ satbk,
    const float* __restrict__ satWv, const float* __restrict__ satbv,
    const float* __restrict__ relWq, const float* __restrict__ relbq,
    int use_cpart) {
    __shared__ float c[32];
    int b   = blockIdx.x % Bn;
    int sel = blockIdx.x / Bn;
    int ks  = blockIdx.y;
    int n   = threadIdx.x;
    int k0  = ks * 32;
    if (n < 32) {
        int k = k0 + n;
        float v;
        if (use_cpart) {
            float s = 0.f;
#pragma unroll
            for (int i = 0; i < 16; i++) s += g_cpart[(b * 16 + i) * Hn + k];
            v = s * (1.f / Ln);
            if (sel == 0) g_center[b * Hn + k] = v;
        } else {
            v = g_center[b * Hn + k];
        }
        c[n] = v;
    }
    __syncthreads();
    const float* W; const float* bi;
    switch (sel) {
        case 0: W = satWk; bi = satbk; break;
        case 1: W = satWv; bi = satbv; break;
        default: W = relWq; bi = relbq; break;
    }
    float s = 0.f;
#pragma unroll
    for (int k = 0; k < 32; k++) s += c[k] * W[(size_t)(k0 + k) * Hn + n];
    if (ks == 0) s += bi[n];
    g_cproj[ks][sel][b * Hn + n] = s;
}

// ---------------------------------------------------------------------------
// rel: w~_bh[k] = SCALE * sum_d Wrk[k][h*32+d] * qrel_bh[d]; s0 = center.w~
// ---------------------------------------------------------------------------
__global__ __launch_bounds__(256)
void rel_wtil_kernel(const float* __restrict__ relWk) {
    __shared__ float q[HDn];
    __shared__ float red[8];
    int bh = blockIdx.x;
    int b = bh >> 3, h = bh & 7;
    int t = threadIdx.x;
    if (t < HDn) {
        int i = b * Hn + h * HDn + t;
        float s = 0.f;
#pragma unroll
        for (int pp = 0; pp < 8; pp++) s += g_cproj[pp][2][i];
        q[t] = s;
    }
    __syncthreads();
    float w = 0.f;
#pragma unroll 8
    for (int d = 0; d < HDn; d++)
        w += relWk[(size_t)t * Hn + h * HDn + d] * q[d];
    w *= SCALE;
    g_wtil[bh * Hn + t] = w;

    float c = g_center[b * Hn + t] * w;
#pragma unroll
    for (int off = 16; off; off >>= 1) c += __shfl_xor_sync(0xffffffffu, c, off);
    if ((t & 31) == 0) red[t >> 5] = c;
    __syncthreads();
    if (t == 0) {
        float tot = 0.f;
#pragma unroll
        for (int i = 0; i < 8; i++) tot += red[i];
        g_sc[bh * SCW] = tot;
    }
}

// ---------------------------------------------------------------------------
// satellite attention, full-width loads: 2 tokens/block, 16 lanes/head,
// __half2 per thread (warp covers 64 consecutive halfs = 128B requests).
// ---------------------------------------------------------------------------
__global__ __launch_bounds__(256)
void sat_attn_kernel(const __half* __restrict__ Kc, const __half* __restrict__ Vc) {
    int tt = threadIdx.x >> 7;                 // token within pair
    int token = blockIdx.x * 2 + tt;
    int b = token >> 12;
    int l = token & (Ln - 1);
    int t128 = threadIdx.x & 127;
    int h = t128 >> 4;                         // head 0..7
    int col = h * HDn + (t128 & 15) * 2;       // even column (half2)

    size_t ic   = (size_t)token * Hn + col;
    int lb = (l + 1) & (Ln - 1);
    int la = (l == 0) ? (Ln - 1) : 0;
    size_t ibe  = ((size_t)(b * Ln + lb)) * Hn + col;
    size_t iaf  = ((size_t)(b * Ln + la)) * Hn + col;
    int icen = b * Hn + col;

    float kcx = 0.f, kcy = 0.f, vcx = 0.f, vcy = 0.f;
#pragma unroll
    for (int pp = 0; pp < 8; pp++) {
        kcx += g_cproj[pp][0][icen];
        kcy += g_cproj[pp][0][icen + 1];
        vcx += g_cproj[pp][1][icen];
        vcy += g_cproj[pp][1][icen + 1];
    }

    float2 q  = __half22float2(*(const __half2*)(g_Qh + ic));
    float2 k0v = __half22float2(*(const __half2*)(Kc + ibe));
    float2 k1v = __half22float2(*(const __half2*)(Kc + ic));
    float2 k2v = __half22float2(*(const __half2*)(Kc + iaf));
    float2 k3v = __half22float2(*(const __half2*)(g_Kxh + ic));

    float s0 = q.x * k0v.x + q.y * k0v.y;
    float s1 = q.x * k1v.x + q.y * k1v.y;
    float s2 = q.x * k2v.x + q.y * k2v.y;
    float s3 = q.x * k3v.x + q.y * k3v.y;
    float s4 = q.x * kcx   + q.y * kcy;
#pragma unroll
    for (int off = 8; off; off >>= 1) {        // reduce within 16-lane head
        s0 += __shfl_xor_sync(0xffffffffu, s0, off);
        s1 += __shfl_xor_sync(0xffffffffu, s1, off);
        s2 += __shfl_xor_sync(0xffffffffu, s2, off);
        s3 += __shfl_xor_sync(0xffffffffu, s3, off);
        s4 += __shfl_xor_sync(0xffffffffu, s4, off);
    }
    s0 *= SCALE; s1 *= SCALE; s2 *= SCALE; s3 *= SCALE; s4 *= SCALE;
    float mx = fmaxf(fmaxf(fmaxf(s0, s1), fmaxf(s2, s3)), s4);
    float e0 = expf(s0 - mx), e1 = expf(s1 - mx), e2 = expf(s2 - mx);
    float e3 = expf(s3 - mx), e4 = expf(s4 - mx);
    float inv = 1.f / (e0 + e1 + e2 + e3 + e4);

    float2 v0v = __half22float2(*(const __half2*)(Vc + ibe));
    float2 v1v = __half22float2(*(const __half2*)(Vc + ic));
    float2 v2v = __half22float2(*(const __half2*)(Vc + iaf));
    float2 v3v = __half22float2(*(const __half2*)(g_Vxh + ic));

    float cx = (e0 * v0v.x + e1 * v1v.x + e2 * v2v.x + e3 * v3v.x + e4 * vcx) * inv;
    float cy = (e0 * v0v.y + e1 * v1v.y + e2 * v2v.y + e3 * v3v.y + e4 * vcy) * inv;

    *(__half2*)(g_ctxP + (size_t)token * KA + col) = __floats2half2_rn(cx, cy);
}

// ---------------------------------------------------------------------------
// rel softmax stats: per bh, max + sum-exp over 4097 scores
// ---------------------------------------------------------------------------
__global__ __launch_bounds__(256)
void rel_stat_kernel() {
    __shared__ float red[8];
    int bh = blockIdx.x;
    int t = threadIdx.x;
    const float* sc = g_sc + bh * SCW;

    float m = -1e30f;
    for (int j = t; j <= Ln; j += 256) m = fmaxf(m, sc[j]);
#pragma unroll
    for (int off = 16; off; off >>= 1)
        m = fmaxf(m, __shfl_xor_sync(0xffffffffu, m, off));
    if ((t & 31) == 0) red[t >> 5] = m;
    __syncthreads();
    float mm = -1e30f;
#pragma unroll
    for (int i = 0; i < 8; i++) mm = fmaxf(mm, red[i]);
    __syncthreads();

    float z = 0.f;
    for (int j = t; j <= Ln; j += 256) z += expf(sc[j] - mm);
#pragma unroll
    for (int off = 16; off; off >>= 1) z += __shfl_xor_sync(0xffffffffu, z, off);
    if ((t & 31) == 0) red[t >> 5] = z;
    __syncthreads();
    if (t == 0) {
        float tot = 0.f;
#pragma unroll
        for (int i = 0; i < 8; i++) tot += red[i];
        g_pm[bh] = mm;
        g_ps[bh] = tot;
    }
}

// ---------------------------------------------------------------------------
// rel weighted row-sum: grid (Bn, NSP=32); 128 keys per chunk.
// ---------------------------------------------------------------------------
__global__ __launch_bounds__(256)
void rel_wsum_kernel() {
    __shared__ float p[8][128];
    __shared__ float mz[16];
    int b = blockIdx.x, sp = blockIdx.y;
    int t = threadIdx.x;
    if (t < 8)       mz[t] = g_pm[b * 8 + t];
    else if (t < 16) mz[t] = 1.f / g_ps[b * 8 + (t - 8)];
    __syncthreads();
    for (int i = t; i < 8 * 128; i += 256) {
        int hh = i >> 7, jj = i & 127;
        p[hh][jj] = expf(g_sc[(b * 8 + hh) * SCW + 1 + sp * 128 + jj] - mz[hh])
                    * mz[8 + hh];
    }
    __syncthreads();

    int h = t >> 5, kg = t & 31;
    float a0x = 0.f, a0y = 0.f, a0z = 0.f, a0w = 0.f;
    float a1x = 0.f, a1y = 0.f, a1z = 0.f, a1w = 0.f;
    for (int jj = 0; jj < 128; jj++) {
        size_t row = (size_t)(b * Ln + sp * 128 + jj) * Hn + kg * 8;
        float4 c0 = *(const float4*)(g_cur + row);
        float4 c1 = *(const float4*)(g_cur + row + 4);
        float pp = p[h][jj];
        a0x += pp * c0.x; a0y += pp * c0.y; a0z += pp * c0.z; a0w += pp * c0.w;
        a1x += pp * c1.x; a1y += pp * c1.y; a1z += pp * c1.z; a1w += pp * c1.w;
    }
    size_t o = (size_t)((b * NSP + sp) * 8 + h) * Hn + kg * 8;
    *(float4*)(g_upart + o)     = make_float4(a0x, a0y, a0z, a0w);
    *(float4*)(g_upart + o + 4) = make_float4(a1x, a1y, a1z, a1w);
}

// ---------------------------------------------------------------------------
// rel epilogue: u = sum_sp upart + p0*center; cx = u@Wrv + bv;
// dst = LN(relu(cx@Wo + bo + center)); also updates g_center
// ---------------------------------------------------------------------------
__global__ __launch_bounds__(256)
void rel_epi_kernel(const float* __restrict__ Wrv, const float* __restrict__ brv,
                    const float* __restrict__ Wo, const float* __restrict__ bo,
                    const float* __restrict__ lnw, const float* __restrict__ lnb,
                    float* __restrict__ dst) {
    __shared__ float u[8][Hn];
    __shared__ float cx[Hn];
    __shared__ float red[8];
    int b = blockIdx.x;
    int n = threadIdx.x;

    float ctr = g_center[b * Hn + n];
#pragma unroll
    for (int h = 0; h < 8; h++) {
        float s = 0.f;
        for (int sp = 0; sp < NSP; sp++)
            s += g_upart[(size_t)((b * NSP + sp) * 8 + h) * Hn + n];
        float p0 = expf(g_sc[(b * 8 + h) * SCW] - g_pm[b * 8 + h]) / g_ps[b * 8 + h];
        u[h][n] = s + p0 * ctr;
    }
    __syncthreads();

    int h = n >> 5;
    float cval = 0.f;
#pragma unroll 8
    for (int k = 0; k < Hn; k++) cval += u[h][k] * Wrv[(size_t)k * Hn + n];
    cx[n] = cval + brv[n];
    __syncthreads();

    float s = 0.f;
#pragma unroll 8
    for (int k = 0; k < Hn; k++) s += cx[k] * Wo[(size_t)k * Hn + n];
    float v = fmaxf(s + bo[n] + ctr, 0.f);

    float r = v;
#pragma unroll
    for (int off = 16; off; off >>= 1) r += __shfl_xor_sync(0xffffffffu, r, off);
    if ((n & 31) == 0) red[n >> 5] = r;
    __syncthreads();
    float tot = 0.f;
#pragma unroll
    for (int i = 0; i < 8; i++) tot += red[i];
    float mean = tot * (1.f / Hn);
    __syncthreads();

    float dv = v - mean;
    float r2 = dv * dv;
#pragma unroll
    for (int off = 16; off; off >>= 1) r2 += __shfl_xor_sync(0xffffffffu, r2, off);
    if ((n & 31) == 0) red[n >> 5] = r2;
    __syncthreads();
    tot = 0.f;
#pragma unroll
    for (int i = 0; i < 8; i++) tot += red[i];
    float var = tot * (1.f / Hn);

    float o = lnw[n] * dv * rsqrtf(var + LNEPS) + lnb[n];
    g_center[b * Hn + n] = o;
    dst[b * Hn + n] = o;
}

// ---------------------------------------------------------------------------
extern "C" void kernel_launch(void* const* d_in, const int* in_sizes, int n_in,
                              void* d_out, int out_size) {
    const float* x     = (const float*)d_in[0];
    const float* satWq = (const float*)d_in[1];  const float* satbq = (const float*)d_in[2];
    const float* satWk = (const float*)d_in[3];  const float* satbk = (const float*)d_in[4];
    const float* satWv = (const float*)d_in[5];  const float* satbv = (const float*)d_in[6];
    const float* satWo = (const float*)d_in[7];  const float* satbo = (const float*)d_in[8];
    const float* relWq = (const float*)d_in[9];  const float* relbq = (const float*)d_in[10];
    const float* relWk = (const float*)d_in[11]; const float* relbk = (const float*)d_in[12];
    const float* relWv = (const float*)d_in[13]; const float* relbv = (const float*)d_in[14];
    const float* relWo = (const float*)d_in[15]; const float* relbo = (const float*)d_in[16];
    const float* slnw  = (const float*)d_in[17]; const float* slnb  = (const float*)d_in[18];
    const float* rlnw  = (const float*)d_in[19]; const float* rlnb  = (const float*)d_in[20];
    float* out = (float*)d_out;
    (void)relbk;   // key bias cancels in softmax

    float *cur, *center;
    __half *curP, *ctxP, *BT, *Qh, *Kch, *Vch, *Kxh, *Vxh;
    cudaGetSymbolAddress((void**)&cur,  g_cur);
    cudaGetSymbolAddress((void**)&curP, g_curP);
    cudaGetSymbolAddress((void**)&ctxP, g_ctxP);
    cudaGetSymbolAddress((void**)&BT,   g_BT);
    cudaGetSymbolAddress((void**)&center, g_center);
    cudaGetSymbolAddress((void**)&Qh,  g_Qh);
    cudaGetSymbolAddress((void**)&Kch, g_Kch);
    cudaGetSymbolAddress((void**)&Vch, g_Vch);
    cudaGetSymbolAddress((void**)&Kxh, g_Kxh);
    cudaGetSymbolAddress((void**)&Vxh, g_Vxh);

    cudaFuncSetAttribute(hgemm_qkv, cudaFuncAttributeMaxDynamicSharedMemorySize,
                         GEMM_SMEM);
    cudaFuncSetAttribute(hgemm_ln, cudaFuncAttributeMaxDynamicSharedMemorySize,
                         LN_SMEM);

    // fp16 weights: 0 satWq, 1 satWk, 2 satWv, 3 satWo
    wprep_kernel<<<dim3(Hn, 4), Hn>>>(satWq, satWk, satWv, satWo);

    splitcopy_kernel<<<Mn * Hn / 8 / 256, 256>>>(x);
    meanpart_kernel<<<dim3(16, Bn), Hn>>>(x);

    const __half* Wq = BT + (size_t)0 * Hn * Hn;
    const __half* Wk = BT + (size_t)1 * Hn * Hn;
    const __half* Wv = BT + (size_t)2 * Hn * Hn;
    const __half* Wo = BT + (size_t)3 * Hn * Hn;

    for (int it = 0; it < 2; it++) {
        proj_center_kernel<<<dim3(3 * Bn, 8), Hn>>>(
            satWk, satbk, satWv, satbv, relWq, relbq, it == 0 ? 1 : 0);
        rel_wtil_kernel<<<Bn * NHn, Hn>>>(relWk);
        __half* Kdst = (it == 0) ? Kxh : Kch;
        __half* Vdst = (it == 0) ? Vxh : Vch;
        hgemm_qkv<<<dim3(Mn / 128, 3), 256, GEMM_SMEM>>>(
            curP, Wq, Wk, Wv, satbq, satbk, satbv, Qh, Kdst, Vdst);
        sat_attn_kernel<<<Mn / 2, 256>>>(Kdst, Vdst);
        float* dup = (it == 0) ? (float*)nullptr : out;
        hgemm_ln<<<Mn / 128, 256, LN_SMEM>>>(ctxP, Wo, satbo, cur, dup, slnw, slnb);

        rel_stat_kernel<<<Bn * NHn, 256>>>();
        rel_wsum_kernel<<<dim3(Bn, NSP), 256>>>();
        float* cdst = (it == 0) ? center : (out + (size_t)Mn * Hn);
        rel_epi_kernel<<<Bn, Hn>>>(relWv, relbv, relWo, relbo, rlnw, rlnb, cdst);
    }
}